// round 1
// baseline (speedup 1.0000x reference)
#include <cuda_runtime.h>
#include <math.h>

// Problem constants
#define T_ 2048
#define E_ 64
#define H_ 8
#define HE_ 512
#define B_ 4
#define BH_ 32

// Device scratch (allocations are forbidden; __device__ globals are the sanctioned path)
__device__ float g_Q[(long long)B_ * T_ * HE_];      // 16 MB  [b,t,h,e]
__device__ float g_K[(long long)B_ * T_ * HE_];      // 16 MB
__device__ float g_V[(long long)B_ * T_ * HE_];      // 16 MB
__device__ float g_S[(long long)BH_ * T_ * T_];      // 512 MB [b,h,t,i]
__device__ float g_cmax[BH_ * T_];                   // per-(b,h,i) column max
__device__ float g_cinvz[BH_ * T_];                  // per-(b,h,i) 1/sum(exp)
__device__ float g_ctx[(long long)B_ * T_ * HE_];    // 16 MB  [b,t,h*e]

// ---------------------------------------------------------------------------
// K1: projections  out[n, m] = X[n, :64] @ W[:64, m],  n in [0,8192), m in [0,512)
// grid (8 Ntiles, 128 Mtiles, 3 matrices), 256 threads, 64x64 tile, K=64 full.
// ---------------------------------------------------------------------------
__global__ void proj_kernel(const float* __restrict__ Xv, const float* __restrict__ Xk,
                            const float* __restrict__ Xq, const float* __restrict__ Wv,
                            const float* __restrict__ Wk, const float* __restrict__ Wq) {
    const float* X;
    const float* W;
    float* O;
    if (blockIdx.z == 0)      { X = Xv; W = Wv; O = g_V; }
    else if (blockIdx.z == 1) { X = Xk; W = Wk; O = g_K; }
    else                      { X = Xq; W = Wq; O = g_Q; }

    __shared__ __align__(16) float Xs[64][68];  // [row n][k]
    __shared__ __align__(16) float Ws[64][68];  // [k][col m]
    const int n0 = blockIdx.y * 64;
    const int m0 = blockIdx.x * 64;
    const int tid = threadIdx.x;

    {
        const int r = tid >> 2, q = tid & 3;
        const float4* xs = reinterpret_cast<const float4*>(X + (size_t)(n0 + r) * 64) + q * 4;
        const float4* ws = reinterpret_cast<const float4*>(W + (size_t)r * HE_ + m0) + q * 4;
#pragma unroll
        for (int j = 0; j < 4; j++) {
            float4 v = xs[j];
            int k = q * 16 + j * 4;
            Xs[r][k] = v.x; Xs[r][k + 1] = v.y; Xs[r][k + 2] = v.z; Xs[r][k + 3] = v.w;
            float4 w = ws[j];
            Ws[r][k] = w.x; Ws[r][k + 1] = w.y; Ws[r][k + 2] = w.z; Ws[r][k + 3] = w.w;
        }
    }
    __syncthreads();

    const int tx = tid & 15, ty = tid >> 4;
    float acc[4][4] = {};
#pragma unroll 8
    for (int k = 0; k < 64; k++) {
        float a[4], b[4];
#pragma unroll
        for (int r = 0; r < 4; r++) a[r] = Xs[ty * 4 + r][k];
#pragma unroll
        for (int c = 0; c < 4; c++) b[c] = Ws[k][tx * 4 + c];
#pragma unroll
        for (int r = 0; r < 4; r++)
#pragma unroll
            for (int c = 0; c < 4; c++) acc[r][c] = fmaf(a[r], b[c], acc[r][c]);
    }
#pragma unroll
    for (int r = 0; r < 4; r++) {
        *reinterpret_cast<float4*>(O + (size_t)(n0 + ty * 4 + r) * HE_ + m0 + tx * 4) =
            make_float4(acc[r][0], acc[r][1], acc[r][2], acc[r][3]);
    }
}

// ---------------------------------------------------------------------------
// K2: scores  S[b,h,t,i] = (Q[b,t,h,:] . K[b,i,h,:]) / 8
// grid (16 i-tiles, 16 t-tiles, 32 bh), 256 threads, 128x128 tile, k-split 2x32.
// ---------------------------------------------------------------------------
__global__ void qk_kernel() {
    const int bh = blockIdx.z, b = bh >> 3, h = bh & 7;
    const float* Qb = g_Q + (size_t)b * T_ * HE_ + h * E_;
    const float* Kb = g_K + (size_t)b * T_ * HE_ + h * E_;
    const int t0 = blockIdx.y * 128, i0 = blockIdx.x * 128;

    __shared__ __align__(16) float Qs[32][132];  // [e][t_local]
    __shared__ __align__(16) float Ks[32][132];  // [e][i_local]
    const int tid = threadIdx.x, tx = tid & 15, ty = tid >> 4;
    const int r = tid >> 1, half = tid & 1;
    float acc[8][8] = {};

#pragma unroll
    for (int ks = 0; ks < 2; ks++) {
        __syncthreads();
        const float4* qs =
            reinterpret_cast<const float4*>(Qb + (size_t)(t0 + r) * HE_ + ks * 32 + half * 16);
        const float4* kk =
            reinterpret_cast<const float4*>(Kb + (size_t)(i0 + r) * HE_ + ks * 32 + half * 16);
#pragma unroll
        for (int j = 0; j < 4; j++) {
            float4 v = qs[j];
            int e = half * 16 + j * 4;
            Qs[e][r] = v.x; Qs[e + 1][r] = v.y; Qs[e + 2][r] = v.z; Qs[e + 3][r] = v.w;
            float4 w = kk[j];
            Ks[e][r] = w.x; Ks[e + 1][r] = w.y; Ks[e + 2][r] = w.z; Ks[e + 3][r] = w.w;
        }
        __syncthreads();
#pragma unroll 4
        for (int e = 0; e < 32; e++) {
            float a[8], bb[8];
#pragma unroll
            for (int rr = 0; rr < 8; rr++) a[rr] = Qs[e][ty * 8 + rr];
#pragma unroll
            for (int c = 0; c < 8; c++) bb[c] = Ks[e][tx * 8 + c];
#pragma unroll
            for (int rr = 0; rr < 8; rr++)
#pragma unroll
                for (int c = 0; c < 8; c++) acc[rr][c] = fmaf(a[rr], bb[c], acc[rr][c]);
        }
    }

    float* Sp = g_S + (size_t)bh * T_ * T_;
#pragma unroll
    for (int rr = 0; rr < 8; rr++) {
        size_t off = (size_t)(t0 + ty * 8 + rr) * T_ + i0 + tx * 8;
        *reinterpret_cast<float4*>(Sp + off) =
            make_float4(acc[rr][0] * 0.125f, acc[rr][1] * 0.125f, acc[rr][2] * 0.125f, acc[rr][3] * 0.125f);
        *reinterpret_cast<float4*>(Sp + off + 4) =
            make_float4(acc[rr][4] * 0.125f, acc[rr][5] * 0.125f, acc[rr][6] * 0.125f, acc[rr][7] * 0.125f);
    }
}

// ---------------------------------------------------------------------------
// K3: column softmax stats over t (axis=2!): per (b,h,i) running max + sumexp.
// Each thread owns one column i; reads are coalesced across threads.
// ---------------------------------------------------------------------------
__global__ void stats_kernel() {
    const int bh = blockIdx.y;
    const int i = blockIdx.x * 256 + threadIdx.x;
    const float* Sp = g_S + (size_t)bh * T_ * T_ + i;
    float m = -3.0e38f, z = 0.0f;
#pragma unroll 4
    for (int t = 0; t < T_; t++) {
        float x = Sp[(size_t)t * T_];
        if (x > m) { z *= __expf(m - x); m = x; }
        z += __expf(x - m);
    }
    g_cmax[bh * T_ + i] = m;
    g_cinvz[bh * T_ + i] = 1.0f / z;
}

// ---------------------------------------------------------------------------
// K4: ctx[b,t,h,e] = sum_i softmaxed(S)[b,h,t,i] * V[b,i,h,e]
// grid (16 t-tiles, 32 bh), 256 threads, 128x64 tile, k-tile 32, 64 k-steps.
// exp/normalize fused into the A-tile load; per-column stats cached in smem.
// ---------------------------------------------------------------------------
__global__ void av_kernel() {
    const int bh = blockIdx.y, b = bh >> 3, h = bh & 7;
    const int t0 = blockIdx.x * 128;
    const float* Sp = g_S + (size_t)bh * T_ * T_;
    const float* Vb = g_V + (size_t)b * T_ * HE_ + h * E_;

    __shared__ __align__(16) float As[32][132];  // [i_local][t_local]
    __shared__ __align__(16) float Vs[32][68];   // [i_local][e]
    __shared__ float smi[T_];
    __shared__ float szi[T_];

    const int tid = threadIdx.x, tx = tid & 15, ty = tid >> 4;
    for (int j = tid; j < T_; j += 256) {
        smi[j] = g_cmax[bh * T_ + j];
        szi[j] = g_cinvz[bh * T_ + j];
    }

    float acc[8][4] = {};
    const int r = tid >> 1, half = tid & 1;
    const int rv = tid >> 3, g = tid & 7;

    for (int kb = 0; kb < 64; kb++) {
        __syncthreads();
        const float4* as =
            reinterpret_cast<const float4*>(Sp + (size_t)(t0 + r) * T_ + kb * 32 + half * 16);
#pragma unroll
        for (int j = 0; j < 4; j++) {
            float4 v = as[j];
            int ic = half * 16 + j * 4;
            int ig = kb * 32 + ic;
            As[ic][r]     = __expf(v.x - smi[ig])     * szi[ig];
            As[ic + 1][r] = __expf(v.y - smi[ig + 1]) * szi[ig + 1];
            As[ic + 2][r] = __expf(v.z - smi[ig + 2]) * szi[ig + 2];
            As[ic + 3][r] = __expf(v.w - smi[ig + 3]) * szi[ig + 3];
        }
        const float4* vs =
            reinterpret_cast<const float4*>(Vb + (size_t)(kb * 32 + rv) * HE_ + g * 8);
        float4 v0 = vs[0], v1 = vs[1];
        Vs[rv][g * 8 + 0] = v0.x; Vs[rv][g * 8 + 1] = v0.y;
        Vs[rv][g * 8 + 2] = v0.z; Vs[rv][g * 8 + 3] = v0.w;
        Vs[rv][g * 8 + 4] = v1.x; Vs[rv][g * 8 + 5] = v1.y;
        Vs[rv][g * 8 + 6] = v1.z; Vs[rv][g * 8 + 7] = v1.w;
        __syncthreads();
#pragma unroll 8
        for (int i2 = 0; i2 < 32; i2++) {
            float a[8], bb[4];
#pragma unroll
            for (int rr = 0; rr < 8; rr++) a[rr] = As[i2][ty * 8 + rr];
#pragma unroll
            for (int c = 0; c < 4; c++) bb[c] = Vs[i2][tx * 4 + c];
#pragma unroll
            for (int rr = 0; rr < 8; rr++)
#pragma unroll
                for (int c = 0; c < 4; c++) acc[rr][c] = fmaf(a[rr], bb[c], acc[rr][c]);
        }
    }

    float* Op = g_ctx + (size_t)b * T_ * HE_ + h * E_;
#pragma unroll
    for (int rr = 0; rr < 8; rr++) {
        *reinterpret_cast<float4*>(Op + (size_t)(t0 + ty * 8 + rr) * HE_ + tx * 4) =
            make_float4(acc[rr][0], acc[rr][1], acc[rr][2], acc[rr][3]);
    }
}

// ---------------------------------------------------------------------------
// K5: out[n, e] = ctx[n, :512] @ Wu[:512, e] + bu[e]
// grid (128 n-tiles), 256 threads, 64x64 tile, k-tile 32, 16 k-steps.
// ---------------------------------------------------------------------------
__global__ void unify_kernel(const float* __restrict__ Wu, const float* __restrict__ bu,
                             float* __restrict__ out) {
    const int n0 = blockIdx.x * 64;
    __shared__ __align__(16) float Cs[32][68];  // [j][n_local]
    __shared__ __align__(16) float Ws[32][68];  // [j][c]
    const int tid = threadIdx.x, tx = tid & 15, ty = tid >> 4;
    float acc[4][4] = {};
    const int r = tid >> 2, q = tid & 3;
    const int rw = tid >> 3, g = tid & 7;

    for (int kb = 0; kb < 16; kb++) {
        __syncthreads();
        const float4* cs =
            reinterpret_cast<const float4*>(g_ctx + (size_t)(n0 + r) * HE_ + kb * 32 + q * 8);
        float4 c0 = cs[0], c1 = cs[1];
        Cs[q * 8 + 0][r] = c0.x; Cs[q * 8 + 1][r] = c0.y;
        Cs[q * 8 + 2][r] = c0.z; Cs[q * 8 + 3][r] = c0.w;
        Cs[q * 8 + 4][r] = c1.x; Cs[q * 8 + 5][r] = c1.y;
        Cs[q * 8 + 6][r] = c1.z; Cs[q * 8 + 7][r] = c1.w;
        const float4* ws =
            reinterpret_cast<const float4*>(Wu + (size_t)(kb * 32 + rw) * 64 + g * 8);
        float4 w0 = ws[0], w1 = ws[1];
        Ws[rw][g * 8 + 0] = w0.x; Ws[rw][g * 8 + 1] = w0.y;
        Ws[rw][g * 8 + 2] = w0.z; Ws[rw][g * 8 + 3] = w0.w;
        Ws[rw][g * 8 + 4] = w1.x; Ws[rw][g * 8 + 5] = w1.y;
        Ws[rw][g * 8 + 6] = w1.z; Ws[rw][g * 8 + 7] = w1.w;
        __syncthreads();
#pragma unroll 8
        for (int j = 0; j < 32; j++) {
            float a[4], bb[4];
#pragma unroll
            for (int rr = 0; rr < 4; rr++) a[rr] = Cs[j][ty * 4 + rr];
#pragma unroll
            for (int c = 0; c < 4; c++) bb[c] = Ws[j][tx * 4 + c];
#pragma unroll
            for (int rr = 0; rr < 4; rr++)
#pragma unroll
                for (int c = 0; c < 4; c++) acc[rr][c] = fmaf(a[rr], bb[c], acc[rr][c]);
        }
    }

    const float b0 = bu[tx * 4 + 0], b1 = bu[tx * 4 + 1];
    const float b2 = bu[tx * 4 + 2], b3 = bu[tx * 4 + 3];
#pragma unroll
    for (int rr = 0; rr < 4; rr++) {
        *reinterpret_cast<float4*>(out + (size_t)(n0 + ty * 4 + rr) * 64 + tx * 4) =
            make_float4(acc[rr][0] + b0, acc[rr][1] + b1, acc[rr][2] + b2, acc[rr][3] + b3);
    }
}

extern "C" void kernel_launch(void* const* d_in, const int* in_sizes, int n_in,
                              void* d_out, int out_size) {
    const float* values  = (const float*)d_in[0];
    const float* keys    = (const float*)d_in[1];
    const float* queries = (const float*)d_in[2];
    const float* Wv      = (const float*)d_in[3];
    const float* Wk      = (const float*)d_in[4];
    const float* Wq      = (const float*)d_in[5];
    const float* Wu      = (const float*)d_in[6];
    const float* bu      = (const float*)d_in[7];
    float* out = (float*)d_out;

    proj_kernel<<<dim3(8, 128, 3), 256>>>(values, keys, queries, Wv, Wk, Wq);
    qk_kernel<<<dim3(16, 16, 32), 256>>>();
    stats_kernel<<<dim3(8, 32), 256>>>();
    av_kernel<<<dim3(16, 32), 256>>>();
    unify_kernel<<<128, 256>>>(Wu, bu, out);
}

// round 3
// speedup vs baseline: 1.4504x; 1.4504x over previous
#include <cuda_runtime.h>
#include <cuda_bf16.h>
#include <math.h>
#include <stdint.h>

#define T_ 2048
#define E_ 64
#define H_ 8
#define HE_ 512
#define B_ 4
#define BH_ 32

// ---------------- device scratch ----------------
__device__ __align__(16) __nv_bfloat16 g_Qh[(size_t)BH_ * T_ * E_];  // [bh][t][e], pre-scaled 1/8
__device__ __align__(16) __nv_bfloat16 g_Ql[(size_t)BH_ * T_ * E_];
__device__ __align__(16) __nv_bfloat16 g_Kh[(size_t)BH_ * T_ * E_];  // [bh][t][e]
__device__ __align__(16) __nv_bfloat16 g_Kl[(size_t)BH_ * T_ * E_];
__device__ __align__(16) __nv_bfloat16 g_Vh[(size_t)BH_ * E_ * T_];  // [bh][e][t] transposed
__device__ __align__(16) __nv_bfloat16 g_Vl[(size_t)BH_ * E_ * T_];
__device__ float g_S[(size_t)BH_ * T_ * T_];      // 512 MB scores
__device__ float g_cstat[BH_ * T_];               // per-(b,h,i): m + ln(z)
__device__ float g_ctx[(size_t)B_ * T_ * HE_];    // [b][t][h*64+e]

__device__ __forceinline__ uint32_t smem_u32(const void* p) {
    uint32_t a;
    asm("{ .reg .u64 t; cvta.to.shared.u64 t, %1; cvt.u32.u64 %0, t; }" : "=r"(a) : "l"(p));
    return a;
}

// ---- warp MMA primitives (sm_80+, valid on base sm_103) ----
__device__ __forceinline__ void ldsm_x4(uint32_t* r, uint32_t addr) {
    asm volatile("ldmatrix.sync.aligned.m8n8.x4.shared.b16 {%0,%1,%2,%3}, [%4];"
                 : "=r"(r[0]), "=r"(r[1]), "=r"(r[2]), "=r"(r[3]) : "r"(addr));
}
__device__ __forceinline__ void ldsm_x2(uint32_t* r, uint32_t addr) {
    asm volatile("ldmatrix.sync.aligned.m8n8.x2.shared.b16 {%0,%1}, [%2];"
                 : "=r"(r[0]), "=r"(r[1]) : "r"(addr));
}
__device__ __forceinline__ void mma_bf16(float* c, const uint32_t* a, const uint32_t* b) {
    asm volatile(
        "mma.sync.aligned.m16n8k16.row.col.f32.bf16.bf16.f32 "
        "{%0,%1,%2,%3}, {%4,%5,%6,%7}, {%8,%9}, {%0,%1,%2,%3};"
        : "+f"(c[0]), "+f"(c[1]), "+f"(c[2]), "+f"(c[3])
        : "r"(a[0]), "r"(a[1]), "r"(a[2]), "r"(a[3]), "r"(b[0]), "r"(b[1]));
}

__device__ __forceinline__ void split2(float x, uint16_t& h, uint16_t& l) {
    __nv_bfloat16 hb = __float2bfloat16(x);
    h = __bfloat16_as_ushort(hb);
    l = __bfloat16_as_ushort(__float2bfloat16(x - __bfloat162float(hb)));
}

// SMEM tile row stride: 72 bf16 = 144 bytes (conflict-free ldmatrix: 144/4 = 36 ≡ 4 mod 32)
#define RS 144

// ---------------------------------------------------------------------------
// K1: projections. 64x64 tile, K=64. z=0:V (split + transpose), 1:K, 2:Q(*0.125)
// ---------------------------------------------------------------------------
__global__ void proj_kernel(const float* __restrict__ Xv, const float* __restrict__ Xk,
                            const float* __restrict__ Xq, const float* __restrict__ Wv,
                            const float* __restrict__ Wk, const float* __restrict__ Wq) {
    const float* X;
    const float* W;
    if (blockIdx.z == 0)      { X = Xv; W = Wv; }
    else if (blockIdx.z == 1) { X = Xk; W = Wk; }
    else                      { X = Xq; W = Wq; }

    __shared__ __align__(16) float Xs[64][68];
    __shared__ __align__(16) float Ws[64][68];
    const int n0 = blockIdx.y * 64;
    const int h  = blockIdx.x;
    const int m0 = h * 64;
    const int b  = n0 >> 11;
    const int t0g = n0 & (T_ - 1);
    const int bh = b * 8 + h;
    const int tid = threadIdx.x;

    {
        const int r = tid >> 2, q = tid & 3;
        const float4* xs = reinterpret_cast<const float4*>(X + (size_t)(n0 + r) * 64) + q * 4;
        const float4* ws = reinterpret_cast<const float4*>(W + (size_t)r * HE_ + m0) + q * 4;
#pragma unroll
        for (int j = 0; j < 4; j++) {
            float4 v = xs[j];
            int k = q * 16 + j * 4;
            Xs[r][k] = v.x; Xs[r][k + 1] = v.y; Xs[r][k + 2] = v.z; Xs[r][k + 3] = v.w;
            float4 w = ws[j];
            Ws[r][k] = w.x; Ws[r][k + 1] = w.y; Ws[r][k + 2] = w.z; Ws[r][k + 3] = w.w;
        }
    }
    __syncthreads();

    const int tx = tid & 15, ty = tid >> 4;
    float acc[4][4] = {};
#pragma unroll 8
    for (int k = 0; k < 64; k++) {
        float a[4], bb[4];
#pragma unroll
        for (int r = 0; r < 4; r++) a[r] = Xs[ty * 4 + r][k];
#pragma unroll
        for (int c = 0; c < 4; c++) bb[c] = Ws[k][tx * 4 + c];
#pragma unroll
        for (int r = 0; r < 4; r++)
#pragma unroll
            for (int c = 0; c < 4; c++) acc[r][c] = fmaf(a[r], bb[c], acc[r][c]);
    }

    if (blockIdx.z == 0) {
        __syncthreads();
#pragma unroll
        for (int r = 0; r < 4; r++)
#pragma unroll
            for (int c = 0; c < 4; c++) Xs[tx * 4 + c][ty * 4 + r] = acc[r][c];
        __syncthreads();
        const int e = tid >> 2, seg = tid & 3;
        uint16_t hi[16], lo[16];
#pragma unroll
        for (int j = 0; j < 16; j++) split2(Xs[e][seg * 16 + j], hi[j], lo[j]);
        size_t base = ((size_t)bh * 64 + e) * T_ + t0g + seg * 16;
        *reinterpret_cast<uint4*>(g_Vh + base)     = *reinterpret_cast<uint4*>(hi);
        *reinterpret_cast<uint4*>(g_Vh + base + 8) = *reinterpret_cast<uint4*>(hi + 8);
        *reinterpret_cast<uint4*>(g_Vl + base)     = *reinterpret_cast<uint4*>(lo);
        *reinterpret_cast<uint4*>(g_Vl + base + 8) = *reinterpret_cast<uint4*>(lo + 8);
    } else {
        __nv_bfloat16* Oh = (blockIdx.z == 1) ? g_Kh : g_Qh;
        __nv_bfloat16* Ol = (blockIdx.z == 1) ? g_Kl : g_Ql;
        const float sc = (blockIdx.z == 2) ? 0.125f : 1.0f;
#pragma unroll
        for (int r = 0; r < 4; r++) {
            uint16_t hi[4], lo[4];
#pragma unroll
            for (int c = 0; c < 4; c++) split2(acc[r][c] * sc, hi[c], lo[c]);
            size_t base = ((size_t)bh * T_ + t0g + ty * 4 + r) * 64 + tx * 4;
            *reinterpret_cast<uint2*>(Oh + base) = *reinterpret_cast<uint2*>(hi);
            *reinterpret_cast<uint2*>(Ol + base) = *reinterpret_cast<uint2*>(lo);
        }
    }
}

// ---------------------------------------------------------------------------
// K2: qk via mma.sync. CTA = (bh, 128 t, 128 i), 256 threads, 8 warps (2M x 4N),
// warp tile 64x32. Split-2 bf16: D = Ah*Bh + Ah*Bl + Al*Bh.
// ---------------------------------------------------------------------------
#define QK_DYN (4 * 128 * RS)
__global__ void __launch_bounds__(256) qk_kernel() {
    extern __shared__ char sm[];
    const int tid = threadIdx.x, wid = tid >> 5, lane = tid & 31;
    const int bh = blockIdx.z;
    const int t0 = blockIdx.y * 128, i0 = blockIdx.x * 128;

    char* sQh = sm;
    char* sQl = sm + 128 * RS;
    char* sKh = sm + 2 * 128 * RS;
    char* sKl = sm + 3 * 128 * RS;

    // load 4 tiles (each 128 rows x 128B) into padded smem
    {
        const uint4* s0 = reinterpret_cast<const uint4*>(g_Qh + ((size_t)bh * T_ + t0) * 64);
        const uint4* s1 = reinterpret_cast<const uint4*>(g_Ql + ((size_t)bh * T_ + t0) * 64);
        const uint4* s2 = reinterpret_cast<const uint4*>(g_Kh + ((size_t)bh * T_ + i0) * 64);
        const uint4* s3 = reinterpret_cast<const uint4*>(g_Kl + ((size_t)bh * T_ + i0) * 64);
#pragma unroll
        for (int j = 0; j < 4; j++) {
            int idx = j * 256 + tid;
            int row = idx >> 3, c = idx & 7;
            int d = row * RS + c * 16;
            *reinterpret_cast<uint4*>(sQh + d) = s0[idx];
            *reinterpret_cast<uint4*>(sQl + d) = s1[idx];
            *reinterpret_cast<uint4*>(sKh + d) = s2[idx];
            *reinterpret_cast<uint4*>(sKl + d) = s3[idx];
        }
    }
    __syncthreads();

    const int wm = (wid & 1) * 64;
    const int wn = (wid >> 1) * 32;
    const int ar = (lane & 7) + ((lane >> 3) & 1) * 8;  // A row within 16
    const int ac = (lane >> 4) * 16;                    // A byte col (0/16)
    const int brow = lane & 7;
    const int bcol = ((lane >> 3) & 1) * 16;

    const uint32_t aQh = smem_u32(sQh), aQl = smem_u32(sQl);
    const uint32_t aKh = smem_u32(sKh), aKl = smem_u32(sKl);

    float acc[4][4][4] = {};
#pragma unroll
    for (int ks = 0; ks < 4; ks++) {
        uint32_t Ah[4][4], Al[4][4], Bh[4][2], Bl[4][2];
#pragma unroll
        for (int mi = 0; mi < 4; mi++) {
            uint32_t off = (uint32_t)((wm + mi * 16 + ar) * RS + ks * 32 + ac);
            ldsm_x4(Ah[mi], aQh + off);
            ldsm_x4(Al[mi], aQl + off);
        }
#pragma unroll
        for (int ni = 0; ni < 4; ni++) {
            uint32_t off = (uint32_t)((wn + ni * 8 + brow) * RS + ks * 32 + bcol);
            ldsm_x2(Bh[ni], aKh + off);
            ldsm_x2(Bl[ni], aKl + off);
        }
#pragma unroll
        for (int mi = 0; mi < 4; mi++)
#pragma unroll
            for (int ni = 0; ni < 4; ni++) {
                mma_bf16(acc[mi][ni], Ah[mi], Bh[ni]);
                mma_bf16(acc[mi][ni], Ah[mi], Bl[ni]);
                mma_bf16(acc[mi][ni], Al[mi], Bh[ni]);
            }
    }

    float* Sp = g_S + (size_t)bh * T_ * T_;
    const int r0 = t0 + wm + (lane >> 2);
    const int c0 = i0 + wn + (lane & 3) * 2;
#pragma unroll
    for (int mi = 0; mi < 4; mi++)
#pragma unroll
        for (int ni = 0; ni < 4; ni++) {
            size_t o = (size_t)(r0 + mi * 16) * T_ + c0 + ni * 8;
            *reinterpret_cast<float2*>(Sp + o) = make_float2(acc[mi][ni][0], acc[mi][ni][1]);
            *reinterpret_cast<float2*>(Sp + o + 8 * T_) = make_float2(acc[mi][ni][2], acc[mi][ni][3]);
        }
}

// ---------------------------------------------------------------------------
// K3: column stats over t: c_i = m_i + ln(z_i)
// ---------------------------------------------------------------------------
__global__ void stats_kernel() {
    const int bh = blockIdx.y;
    const int i = blockIdx.x * 256 + threadIdx.x;
    const float* Sp = g_S + (size_t)bh * T_ * T_ + i;
    float m = -3.0e38f, z = 0.0f;
#pragma unroll 4
    for (int t = 0; t < T_; t++) {
        float x = Sp[(size_t)t * T_];
        if (x > m) { z *= __expf(m - x); m = x; }
        z += __expf(x - m);
    }
    g_cstat[bh * T_ + i] = m + __logf(z);
}

// ---------------------------------------------------------------------------
// K4: av via mma.sync. CTA = (bh, 128 t), loop i in chunks of 64.
// P = exp(S - c_i) split bf16; V pre-transposed [bh][e][i].
// 8 warps (2M x 4N), warp tile 64x16.
// ---------------------------------------------------------------------------
#define AV_PH 0
#define AV_PL (128 * RS)
#define AV_VH (2 * 128 * RS)
#define AV_VL (2 * 128 * RS + 64 * RS)
#define AV_CS (2 * 128 * RS + 2 * 64 * RS)
#define AV_DYN (AV_CS + T_ * 4)
__global__ void __launch_bounds__(256) av_kernel() {
    extern __shared__ char sm[];
    const int tid = threadIdx.x, wid = tid >> 5, lane = tid & 31;
    const int bh = blockIdx.y, b = bh >> 3, h = bh & 7;
    const int t0 = blockIdx.x * 128;

    float* cs = reinterpret_cast<float*>(sm + AV_CS);
#pragma unroll
    for (int j = 0; j < 8; j++) cs[j * 256 + tid] = g_cstat[bh * T_ + j * 256 + tid];

    const float* Sp = g_S + (size_t)bh * T_ * T_;
    const char* Vhp = reinterpret_cast<const char*>(g_Vh + (size_t)bh * 64 * T_);
    const char* Vlp = reinterpret_cast<const char*>(g_Vl + (size_t)bh * 64 * T_);

    const int wm = (wid & 1) * 64;
    const int wn = (wid >> 1) * 16;
    const int ar = (lane & 7) + ((lane >> 3) & 1) * 8;
    const int ac = (lane >> 4) * 16;
    const int brow = lane & 7;
    const int bcol = ((lane >> 3) & 1) * 16;

    const uint32_t aPh = smem_u32(sm + AV_PH), aPl = smem_u32(sm + AV_PL);
    const uint32_t aVh = smem_u32(sm + AV_VH), aVl = smem_u32(sm + AV_VL);

    const int prow = tid >> 1, phalf = tid & 1;  // P fill mapping

    float acc[4][2][4] = {};

    for (int kc = 0; kc < 32; kc++) {
        const int i0 = kc * 64;
        __syncthreads();  // protect smem from previous chunk's mma reads

        // S -> P (exp + split) : thread handles row prow, 32 i-values
        {
            const float* srow = Sp + (size_t)(t0 + prow) * T_ + i0 + phalf * 32;
            const float* crow = cs + i0 + phalf * 32;
            char* dh = sm + AV_PH + prow * RS + phalf * 64;
            char* dl = sm + AV_PL + prow * RS + phalf * 64;
#pragma unroll
            for (int j = 0; j < 8; j++) {
                float4 s = *reinterpret_cast<const float4*>(srow + j * 4);
                float p0 = __expf(s.x - crow[j * 4 + 0]);
                float p1 = __expf(s.y - crow[j * 4 + 1]);
                float p2 = __expf(s.z - crow[j * 4 + 2]);
                float p3 = __expf(s.w - crow[j * 4 + 3]);
                uint16_t h0, h1, h2, h3, l0, l1, l2, l3;
                split2(p0, h0, l0); split2(p1, h1, l1);
                split2(p2, h2, l2); split2(p3, h3, l3);
                uint2 hh, ll;
                hh.x = (uint32_t)h0 | ((uint32_t)h1 << 16);
                hh.y = (uint32_t)h2 | ((uint32_t)h3 << 16);
                ll.x = (uint32_t)l0 | ((uint32_t)l1 << 16);
                ll.y = (uint32_t)l2 | ((uint32_t)l3 << 16);
                *reinterpret_cast<uint2*>(dh + j * 8) = hh;
                *reinterpret_cast<uint2*>(dl + j * 8) = ll;
            }
        }
        // V tiles: 64 rows (e) x 64 bf16 (i) = 512 uint4 each
#pragma unroll
        for (int j = 0; j < 2; j++) {
            int idx = j * 256 + tid;
            int e = idx >> 3, c = idx & 7;
            size_t gsrc = (size_t)e * T_ * 2 + (size_t)i0 * 2 + c * 16;
            int d = e * RS + c * 16;
            *reinterpret_cast<uint4*>(sm + AV_VH + d) = *reinterpret_cast<const uint4*>(Vhp + gsrc);
            *reinterpret_cast<uint4*>(sm + AV_VL + d) = *reinterpret_cast<const uint4*>(Vlp + gsrc);
        }
        __syncthreads();

#pragma unroll
        for (int ks = 0; ks < 4; ks++) {
            uint32_t Ah[4][4], Al[4][4], Bh[2][2], Bl[2][2];
#pragma unroll
            for (int mi = 0; mi < 4; mi++) {
                uint32_t off = (uint32_t)((wm + mi * 16 + ar) * RS + ks * 32 + ac);
                ldsm_x4(Ah[mi], aPh + off);
                ldsm_x4(Al[mi], aPl + off);
            }
#pragma unroll
            for (int ni = 0; ni < 2; ni++) {
                uint32_t off = (uint32_t)((wn + ni * 8 + brow) * RS + ks * 32 + bcol);
                ldsm_x2(Bh[ni], aVh + off);
                ldsm_x2(Bl[ni], aVl + off);
            }
#pragma unroll
            for (int mi = 0; mi < 4; mi++)
#pragma unroll
                for (int ni = 0; ni < 2; ni++) {
                    mma_bf16(acc[mi][ni], Ah[mi], Bh[ni]);
                    mma_bf16(acc[mi][ni], Ah[mi], Bl[ni]);
                    mma_bf16(acc[mi][ni], Al[mi], Bh[ni]);
                }
        }
    }

    // epilogue -> g_ctx[b][t][h*64+e]
    const int r0 = t0 + wm + (lane >> 2);
    const int c0 = h * 64 + wn + (lane & 3) * 2;
#pragma unroll
    for (int mi = 0; mi < 4; mi++)
#pragma unroll
        for (int ni = 0; ni < 2; ni++) {
            size_t o = ((size_t)b * T_ + r0 + mi * 16) * HE_ + c0 + ni * 8;
            *reinterpret_cast<float2*>(g_ctx + o) = make_float2(acc[mi][ni][0], acc[mi][ni][1]);
            *reinterpret_cast<float2*>(g_ctx + o + 8 * HE_) =
                make_float2(acc[mi][ni][2], acc[mi][ni][3]);
        }
}

// ---------------------------------------------------------------------------
// K5: out = ctx @ Wu + bu
// ---------------------------------------------------------------------------
__global__ void unify_kernel(const float* __restrict__ Wu, const float* __restrict__ bu,
                             float* __restrict__ out) {
    const int n0 = blockIdx.x * 64;
    __shared__ __align__(16) float Cs[32][68];
    __shared__ __align__(16) float Ws[32][68];
    const int tid = threadIdx.x, tx = tid & 15, ty = tid >> 4;
    float acc[4][4] = {};
    const int r = tid >> 2, q = tid & 3;
    const int rw = tid >> 3, g = tid & 7;

    for (int kb = 0; kb < 16; kb++) {
        __syncthreads();
        const float4* csp =
            reinterpret_cast<const float4*>(g_ctx + (size_t)(n0 + r) * HE_ + kb * 32 + q * 8);
        float4 c0 = csp[0], c1 = csp[1];
        Cs[q * 8 + 0][r] = c0.x; Cs[q * 8 + 1][r] = c0.y;
        Cs[q * 8 + 2][r] = c0.z; Cs[q * 8 + 3][r] = c0.w;
        Cs[q * 8 + 4][r] = c1.x; Cs[q * 8 + 5][r] = c1.y;
        Cs[q * 8 + 6][r] = c1.z; Cs[q * 8 + 7][r] = c1.w;
        const float4* ws =
            reinterpret_cast<const float4*>(Wu + (size_t)(kb * 32 + rw) * 64 + g * 8);
        float4 w0 = ws[0], w1 = ws[1];
        Ws[rw][g * 8 + 0] = w0.x; Ws[rw][g * 8 + 1] = w0.y;
        Ws[rw][g * 8 + 2] = w0.z; Ws[rw][g * 8 + 3] = w0.w;
        Ws[rw][g * 8 + 4] = w1.x; Ws[rw][g * 8 + 5] = w1.y;
        Ws[rw][g * 8 + 6] = w1.z; Ws[rw][g * 8 + 7] = w1.w;
        __syncthreads();
#pragma unroll 8
        for (int j = 0; j < 32; j++) {
            float a[4], bb[4];
#pragma unroll
            for (int rr = 0; rr < 4; rr++) a[rr] = Cs[j][ty * 4 + rr];
#pragma unroll
            for (int c = 0; c < 4; c++) bb[c] = Ws[j][tx * 4 + c];
#pragma unroll
            for (int rr = 0; rr < 4; rr++)
#pragma unroll
                for (int c = 0; c < 4; c++) acc[rr][c] = fmaf(a[rr], bb[c], acc[rr][c]);
        }
    }

    const float b0 = bu[tx * 4 + 0], b1 = bu[tx * 4 + 1];
    const float b2 = bu[tx * 4 + 2], b3 = bu[tx * 4 + 3];
#pragma unroll
    for (int rr = 0; rr < 4; rr++) {
        *reinterpret_cast<float4*>(out + (size_t)(n0 + ty * 4 + rr) * 64 + tx * 4) =
            make_float4(acc[rr][0] + b0, acc[rr][1] + b1, acc[rr][2] + b2, acc[rr][3] + b3);
    }
}

extern "C" void kernel_launch(void* const* d_in, const int* in_sizes, int n_in,
                              void* d_out, int out_size) {
    const float* values  = (const float*)d_in[0];
    const float* keys    = (const float*)d_in[1];
    const float* queries = (const float*)d_in[2];
    const float* Wv      = (const float*)d_in[3];
    const float* Wk      = (const float*)d_in[4];
    const float* Wq      = (const float*)d_in[5];
    const float* Wu      = (const float*)d_in[6];
    const float* bu      = (const float*)d_in[7];
    float* out = (float*)d_out;

    cudaFuncSetAttribute(qk_kernel, cudaFuncAttributeMaxDynamicSharedMemorySize, QK_DYN);
    cudaFuncSetAttribute(av_kernel, cudaFuncAttributeMaxDynamicSharedMemorySize, AV_DYN);

    proj_kernel<<<dim3(8, 128, 3), 256>>>(values, keys, queries, Wv, Wk, Wq);
    qk_kernel<<<dim3(16, 16, 32), 256, QK_DYN>>>();
    stats_kernel<<<dim3(8, 32), 256>>>();
    av_kernel<<<dim3(16, 32), 256, AV_DYN>>>();
    unify_kernel<<<128, 256>>>(Wu, bu, out);
}

// round 4
// speedup vs baseline: 4.6579x; 3.2115x over previous
#include <cuda_runtime.h>
#include <cuda_fp16.h>
#include <math.h>
#include <stdint.h>

#define T_ 2048
#define E_ 64
#define H_ 8
#define HE_ 512
#define B_ 4
#define BH_ 32

// ---------------- device scratch ----------------
__device__ __align__(16) __half g_Q[(size_t)BH_ * T_ * E_];  // [bh][t][e], pre-scaled 1/8
__device__ __align__(16) __half g_K[(size_t)BH_ * T_ * E_];  // [bh][t][e]
__device__ __align__(16) __half g_V[(size_t)BH_ * E_ * T_];  // [bh][e][t] transposed
__device__ float g_cinvz[BH_ * T_];                          // per-(bh,i): 1/sum_t exp(S[t,i])
__device__ float g_ctx[(size_t)B_ * T_ * HE_];               // [b][t][h*64+e]

__device__ __forceinline__ uint32_t smem_u32(const void* p) {
    uint32_t a;
    asm("{ .reg .u64 t; cvta.to.shared.u64 t, %1; cvt.u32.u64 %0, t; }" : "=r"(a) : "l"(p));
    return a;
}

// ---- warp MMA primitives (sm_80+, valid on base sm_103) ----
__device__ __forceinline__ void ldsm_x4(uint32_t* r, uint32_t addr) {
    asm volatile("ldmatrix.sync.aligned.m8n8.x4.shared.b16 {%0,%1,%2,%3}, [%4];"
                 : "=r"(r[0]), "=r"(r[1]), "=r"(r[2]), "=r"(r[3]) : "r"(addr));
}
__device__ __forceinline__ void ldsm_x2(uint32_t* r, uint32_t addr) {
    asm volatile("ldmatrix.sync.aligned.m8n8.x2.shared.b16 {%0,%1}, [%2];"
                 : "=r"(r[0]), "=r"(r[1]) : "r"(addr));
}
__device__ __forceinline__ void mma_f16(float* c, const uint32_t* a, const uint32_t* b) {
    asm volatile(
        "mma.sync.aligned.m16n8k16.row.col.f32.f16.f16.f32 "
        "{%0,%1,%2,%3}, {%4,%5,%6,%7}, {%8,%9}, {%0,%1,%2,%3};"
        : "+f"(c[0]), "+f"(c[1]), "+f"(c[2]), "+f"(c[3])
        : "r"(a[0]), "r"(a[1]), "r"(a[2]), "r"(a[3]), "r"(b[0]), "r"(b[1]));
}
__device__ __forceinline__ uint32_t pack_h2(float a, float b) {
    __half2 h = __floats2half2_rn(a, b);
    return *reinterpret_cast<uint32_t*>(&h);
}

// SMEM tile row stride: 128B data + 16B pad (conflict-free ldmatrix)
#define RS 144

// ---------------------------------------------------------------------------
// K1: projections. 64x64 tile, K=64. z=0:V (fp16 + transpose), 1:K, 2:Q(*0.125)
// ---------------------------------------------------------------------------
__global__ void proj_kernel(const float* __restrict__ Xv, const float* __restrict__ Xk,
                            const float* __restrict__ Xq, const float* __restrict__ Wv,
                            const float* __restrict__ Wk, const float* __restrict__ Wq) {
    const float* X;
    const float* W;
    if (blockIdx.z == 0)      { X = Xv; W = Wv; }
    else if (blockIdx.z == 1) { X = Xk; W = Wk; }
    else                      { X = Xq; W = Wq; }

    __shared__ __align__(16) float Xs[64][68];
    __shared__ __align__(16) float Ws[64][68];
    const int n0 = blockIdx.y * 64;
    const int h  = blockIdx.x;
    const int m0 = h * 64;
    const int b  = n0 >> 11;
    const int t0g = n0 & (T_ - 1);
    const int bh = b * 8 + h;
    const int tid = threadIdx.x;

    {
        const int r = tid >> 2, q = tid & 3;
        const float4* xs = reinterpret_cast<const float4*>(X + (size_t)(n0 + r) * 64) + q * 4;
        const float4* ws = reinterpret_cast<const float4*>(W + (size_t)r * HE_ + m0) + q * 4;
#pragma unroll
        for (int j = 0; j < 4; j++) {
            float4 v = xs[j];
            int k = q * 16 + j * 4;
            Xs[r][k] = v.x; Xs[r][k + 1] = v.y; Xs[r][k + 2] = v.z; Xs[r][k + 3] = v.w;
            float4 w = ws[j];
            Ws[r][k] = w.x; Ws[r][k + 1] = w.y; Ws[r][k + 2] = w.z; Ws[r][k + 3] = w.w;
        }
    }
    __syncthreads();

    const int tx = tid & 15, ty = tid >> 4;
    float acc[4][4] = {};
#pragma unroll 8
    for (int k = 0; k < 64; k++) {
        float a[4], bb[4];
#pragma unroll
        for (int r = 0; r < 4; r++) a[r] = Xs[ty * 4 + r][k];
#pragma unroll
        for (int c = 0; c < 4; c++) bb[c] = Ws[k][tx * 4 + c];
#pragma unroll
        for (int r = 0; r < 4; r++)
#pragma unroll
            for (int c = 0; c < 4; c++) acc[r][c] = fmaf(a[r], bb[c], acc[r][c]);
    }

    if (blockIdx.z == 0) {
        // V: transpose in SMEM (reuse Xs as [e][t]), then fp16 rows of t
        __syncthreads();
#pragma unroll
        for (int r = 0; r < 4; r++)
#pragma unroll
            for (int c = 0; c < 4; c++) Xs[tx * 4 + c][ty * 4 + r] = acc[r][c];
        __syncthreads();
        const int e = tid >> 2, seg = tid & 3;
        ushort hv[16];
#pragma unroll
        for (int j = 0; j < 16; j++) {
            __half hh = __float2half_rn(Xs[e][seg * 16 + j]);
            hv[j] = *reinterpret_cast<ushort*>(&hh);
        }
        size_t base = ((size_t)bh * 64 + e) * T_ + t0g + seg * 16;
        *reinterpret_cast<uint4*>(g_V + base)     = *reinterpret_cast<uint4*>(hv);
        *reinterpret_cast<uint4*>(g_V + base + 8) = *reinterpret_cast<uint4*>(hv + 8);
    } else {
        __half* O = (blockIdx.z == 1) ? g_K : g_Q;
        const float sc = (blockIdx.z == 2) ? 0.125f : 1.0f;
#pragma unroll
        for (int r = 0; r < 4; r++) {
            ushort hv[4];
#pragma unroll
            for (int c = 0; c < 4; c++) {
                __half hh = __float2half_rn(acc[r][c] * sc);
                hv[c] = *reinterpret_cast<ushort*>(&hh);
            }
            size_t base = ((size_t)bh * T_ + t0g + ty * 4 + r) * 64 + tx * 4;
            *reinterpret_cast<uint2*>(O + base) = *reinterpret_cast<uint2*>(hv);
        }
    }
}

// ---------------------------------------------------------------------------
// K2: column sums. CTA = (i-block 128, bh). K block resident, Q streamed in
// 16 chunks of 128 t. For each chunk: S tile via MMA, z[col] += exp(s).
// No max subtraction (scores ~N(0,0.3); fp32 exp range is ample).
// ---------------------------------------------------------------------------
#define CS_SK 0
#define CS_SQ (128 * RS)
#define CS_ZB (2 * 128 * RS)
#define CS_DYN (CS_ZB + 256 * 4)
__global__ void __launch_bounds__(256) colsum_kernel() {
    extern __shared__ char sm[];
    const int tid = threadIdx.x, wid = tid >> 5, lane = tid & 31;
    const int bh = blockIdx.y;
    const int i0 = blockIdx.x * 128;

    const __half* Qg = g_Q + (size_t)bh * T_ * 64;
    const __half* Kg = g_K + (size_t)bh * T_ * 64;
    float* zbuf = reinterpret_cast<float*>(sm + CS_ZB);

    // K block resident: 128 rows x 8 uint4
#pragma unroll
    for (int j = 0; j < 4; j++) {
        int idx = j * 256 + tid;
        int row = idx >> 3, c = idx & 7;
        *reinterpret_cast<uint4*>(sm + CS_SK + row * RS + c * 16) =
            *reinterpret_cast<const uint4*>(Kg + (size_t)(i0 + row) * 64 + c * 8);
    }

    const int wm = (wid & 1) * 64;
    const int wn = (wid >> 1) * 32;
    const int ar = (lane & 7) + ((lane >> 3) & 1) * 8;
    const int ac = (lane >> 4) * 16;
    const int brow = lane & 7;
    const int bcol = ((lane >> 3) & 1) * 16;
    const uint32_t aK = smem_u32(sm + CS_SK);
    const uint32_t aQ = smem_u32(sm + CS_SQ);

    float z[8] = {};

    for (int tc = 0; tc < 16; tc++) {
        __syncthreads();
#pragma unroll
        for (int j = 0; j < 4; j++) {
            int idx = j * 256 + tid;
            int row = idx >> 3, c = idx & 7;
            *reinterpret_cast<uint4*>(sm + CS_SQ + row * RS + c * 16) =
                *reinterpret_cast<const uint4*>(Qg + (size_t)(tc * 128 + row) * 64 + c * 8);
        }
        __syncthreads();

        float acc[4][4][4] = {};
#pragma unroll
        for (int ks = 0; ks < 4; ks++) {
            uint32_t A[4][4], Bf[4][2];
#pragma unroll
            for (int mi = 0; mi < 4; mi++)
                ldsm_x4(A[mi], aQ + (uint32_t)((wm + mi * 16 + ar) * RS + ks * 32 + ac));
#pragma unroll
            for (int ni = 0; ni < 4; ni++)
                ldsm_x2(Bf[ni], aK + (uint32_t)((wn + ni * 8 + brow) * RS + ks * 32 + bcol));
#pragma unroll
            for (int mi = 0; mi < 4; mi++)
#pragma unroll
                for (int ni = 0; ni < 4; ni++) mma_f16(acc[mi][ni], A[mi], Bf[ni]);
        }
#pragma unroll
        for (int ni = 0; ni < 4; ni++) {
            float e0 = 0.f, e1 = 0.f;
#pragma unroll
            for (int mi = 0; mi < 4; mi++) {
                e0 += __expf(acc[mi][ni][0]) + __expf(acc[mi][ni][2]);
                e1 += __expf(acc[mi][ni][1]) + __expf(acc[mi][ni][3]);
            }
            z[ni * 2] += e0;
            z[ni * 2 + 1] += e1;
        }
    }

    // reduce over the 8 lanes sharing (lane & 3)
#pragma unroll
    for (int c = 0; c < 8; c++) {
        z[c] += __shfl_xor_sync(0xffffffffu, z[c], 4);
        z[c] += __shfl_xor_sync(0xffffffffu, z[c], 8);
        z[c] += __shfl_xor_sync(0xffffffffu, z[c], 16);
    }
    __syncthreads();
    if (lane < 4) {
#pragma unroll
        for (int ni = 0; ni < 4; ni++) {
            zbuf[wid * 32 + ni * 8 + lane * 2]     = z[ni * 2];
            zbuf[wid * 32 + ni * 8 + lane * 2 + 1] = z[ni * 2 + 1];
        }
    }
    __syncthreads();
    if (tid < 128) {
        int col = tid;
        int wg = col >> 5, local = col & 31;
        float zt = zbuf[(2 * wg) * 32 + local] + zbuf[(2 * wg + 1) * 32 + local];
        g_cinvz[bh * T_ + i0 + col] = 1.0f / zt;
    }
}

// ---------------------------------------------------------------------------
// K3: av. CTA = (t-block 128, bh). Q resident; loop i chunks of 64:
//   recompute S tile (MMA), P = exp(s)*invz in regs -> fp16 smem, MMA P*V.
// ---------------------------------------------------------------------------
#define AV_SQ 0
#define AV_SK (128 * RS)
#define AV_SP (128 * RS + 64 * RS)
#define AV_SV (2 * 128 * RS + 64 * RS)
#define AV_IZ (2 * 128 * RS + 2 * 64 * RS)
#define AV_DYN (AV_IZ + 64 * 4)
__global__ void __launch_bounds__(256) av_kernel() {
    extern __shared__ char sm[];
    const int tid = threadIdx.x, wid = tid >> 5, lane = tid & 31;
    const int bh = blockIdx.y, b = bh >> 3, h = bh & 7;
    const int t0 = blockIdx.x * 128;

    const __half* Qg = g_Q + (size_t)bh * T_ * 64;
    const __half* Kg = g_K + (size_t)bh * T_ * 64;
    const __half* Vg = g_V + (size_t)bh * 64 * T_;
    float* sInvz = reinterpret_cast<float*>(sm + AV_IZ);

    // Q block resident
#pragma unroll
    for (int j = 0; j < 4; j++) {
        int idx = j * 256 + tid;
        int row = idx >> 3, c = idx & 7;
        *reinterpret_cast<uint4*>(sm + AV_SQ + row * RS + c * 16) =
            *reinterpret_cast<const uint4*>(Qg + (size_t)(t0 + row) * 64 + c * 8);
    }

    const int wm = (wid & 1) * 64;
    const int wn = (wid >> 1) * 16;  // used for both S cols (i) and O cols (e)
    const int ar = (lane & 7) + ((lane >> 3) & 1) * 8;
    const int ac = (lane >> 4) * 16;
    const int brow = lane & 7;
    const int bcol = ((lane >> 3) & 1) * 16;
    const uint32_t aQ = smem_u32(sm + AV_SQ);
    const uint32_t aK = smem_u32(sm + AV_SK);
    const uint32_t aP = smem_u32(sm + AV_SP);
    const uint32_t aV = smem_u32(sm + AV_SV);

    float acc_o[4][2][4] = {};

    for (int kc = 0; kc < 32; kc++) {
        const int i0 = kc * 64;
        __syncthreads();  // previous chunk's MMA reads done
        // K chunk (64 i-rows) and V chunk (64 e-rows)
#pragma unroll
        for (int j = 0; j < 2; j++) {
            int idx = j * 256 + tid;
            int row = idx >> 3, c = idx & 7;
            *reinterpret_cast<uint4*>(sm + AV_SK + row * RS + c * 16) =
                *reinterpret_cast<const uint4*>(Kg + (size_t)(i0 + row) * 64 + c * 8);
            *reinterpret_cast<uint4*>(sm + AV_SV + row * RS + c * 16) =
                *reinterpret_cast<const uint4*>(Vg + (size_t)row * T_ + i0 + c * 8);
        }
        if (tid < 64) sInvz[tid] = g_cinvz[bh * T_ + i0 + tid];
        __syncthreads();

        // S tile: 128t x 64i
        float acc_s[4][2][4] = {};
#pragma unroll
        for (int ks = 0; ks < 4; ks++) {
            uint32_t A[4][4], Bf[2][2];
#pragma unroll
            for (int mi = 0; mi < 4; mi++)
                ldsm_x4(A[mi], aQ + (uint32_t)((wm + mi * 16 + ar) * RS + ks * 32 + ac));
#pragma unroll
            for (int ni = 0; ni < 2; ni++)
                ldsm_x2(Bf[ni], aK + (uint32_t)((wn + ni * 8 + brow) * RS + ks * 32 + bcol));
#pragma unroll
            for (int mi = 0; mi < 4; mi++)
#pragma unroll
                for (int ni = 0; ni < 2; ni++) mma_f16(acc_s[mi][ni], A[mi], Bf[ni]);
        }

        // P = exp(s) * invz -> fp16 smem
#pragma unroll
        for (int ni = 0; ni < 2; ni++) {
            const int col0 = wn + ni * 8 + (lane & 3) * 2;
            const float iv0 = sInvz[col0], iv1 = sInvz[col0 + 1];
#pragma unroll
            for (int mi = 0; mi < 4; mi++) {
                const int r = wm + mi * 16 + (lane >> 2);
                uint32_t h01 = pack_h2(__expf(acc_s[mi][ni][0]) * iv0,
                                       __expf(acc_s[mi][ni][1]) * iv1);
                uint32_t h23 = pack_h2(__expf(acc_s[mi][ni][2]) * iv0,
                                       __expf(acc_s[mi][ni][3]) * iv1);
                *reinterpret_cast<uint32_t*>(sm + AV_SP + r * RS + col0 * 2) = h01;
                *reinterpret_cast<uint32_t*>(sm + AV_SP + (r + 8) * RS + col0 * 2) = h23;
            }
        }
        __syncthreads();

        // O += P * V  (128t x 64e, k = 64 i)
#pragma unroll
        for (int ks = 0; ks < 4; ks++) {
            uint32_t A[4][4], Bf[2][2];
#pragma unroll
            for (int mi = 0; mi < 4; mi++)
                ldsm_x4(A[mi], aP + (uint32_t)((wm + mi * 16 + ar) * RS + ks * 32 + ac));
#pragma unroll
            for (int ni = 0; ni < 2; ni++)
                ldsm_x2(Bf[ni], aV + (uint32_t)((wn + ni * 8 + brow) * RS + ks * 32 + bcol));
#pragma unroll
            for (int mi = 0; mi < 4; mi++)
#pragma unroll
                for (int ni = 0; ni < 2; ni++) mma_f16(acc_o[mi][ni], A[mi], Bf[ni]);
        }
    }

    // epilogue -> g_ctx[b][t][h*64+e]
    const int r0 = t0 + wm + (lane >> 2);
    const int c0 = h * 64 + wn + (lane & 3) * 2;
#pragma unroll
    for (int mi = 0; mi < 4; mi++)
#pragma unroll
        for (int ni = 0; ni < 2; ni++) {
            size_t o = ((size_t)b * T_ + r0 + mi * 16) * HE_ + c0 + ni * 8;
            *reinterpret_cast<float2*>(g_ctx + o) = make_float2(acc_o[mi][ni][0], acc_o[mi][ni][1]);
            *reinterpret_cast<float2*>(g_ctx + o + 8 * HE_) =
                make_float2(acc_o[mi][ni][2], acc_o[mi][ni][3]);
        }
}

// ---------------------------------------------------------------------------
// K4: out = ctx @ Wu + bu
// ---------------------------------------------------------------------------
__global__ void unify_kernel(const float* __restrict__ Wu, const float* __restrict__ bu,
                             float* __restrict__ out) {
    const int n0 = blockIdx.x * 64;
    __shared__ __align__(16) float Cs[32][68];
    __shared__ __align__(16) float Ws[32][68];
    const int tid = threadIdx.x, tx = tid & 15, ty = tid >> 4;
    float acc[4][4] = {};
    const int r = tid >> 2, q = tid & 3;
    const int rw = tid >> 3, g = tid & 7;

    for (int kb = 0; kb < 16; kb++) {
        __syncthreads();
        const float4* csp =
            reinterpret_cast<const float4*>(g_ctx + (size_t)(n0 + r) * HE_ + kb * 32 + q * 8);
        float4 c0 = csp[0], c1 = csp[1];
        Cs[q * 8 + 0][r] = c0.x; Cs[q * 8 + 1][r] = c0.y;
        Cs[q * 8 + 2][r] = c0.z; Cs[q * 8 + 3][r] = c0.w;
        Cs[q * 8 + 4][r] = c1.x; Cs[q * 8 + 5][r] = c1.y;
        Cs[q * 8 + 6][r] = c1.z; Cs[q * 8 + 7][r] = c1.w;
        const float4* ws =
            reinterpret_cast<const float4*>(Wu + (size_t)(kb * 32 + rw) * 64 + g * 8);
        float4 w0 = ws[0], w1 = ws[1];
        Ws[rw][g * 8 + 0] = w0.x; Ws[rw][g * 8 + 1] = w0.y;
        Ws[rw][g * 8 + 2] = w0.z; Ws[rw][g * 8 + 3] = w0.w;
        Ws[rw][g * 8 + 4] = w1.x; Ws[rw][g * 8 + 5] = w1.y;
        Ws[rw][g * 8 + 6] = w1.z; Ws[rw][g * 8 + 7] = w1.w;
        __syncthreads();
#pragma unroll 8
        for (int j = 0; j < 32; j++) {
            float a[4], bb[4];
#pragma unroll
            for (int rr = 0; rr < 4; rr++) a[rr] = Cs[j][ty * 4 + rr];
#pragma unroll
            for (int c = 0; c < 4; c++) bb[c] = Ws[j][tx * 4 + c];
#pragma unroll
            for (int rr = 0; rr < 4; rr++)
#pragma unroll
                for (int c = 0; c < 4; c++) acc[rr][c] = fmaf(a[rr], bb[c], acc[rr][c]);
        }
    }

    const float b0 = bu[tx * 4 + 0], b1 = bu[tx * 4 + 1];
    const float b2 = bu[tx * 4 + 2], b3 = bu[tx * 4 + 3];
#pragma unroll
    for (int rr = 0; rr < 4; rr++) {
        *reinterpret_cast<float4*>(out + (size_t)(n0 + ty * 4 + rr) * 64 + tx * 4) =
            make_float4(acc[rr][0] + b0, acc[rr][1] + b1, acc[rr][2] + b2, acc[rr][3] + b3);
    }
}

extern "C" void kernel_launch(void* const* d_in, const int* in_sizes, int n_in,
                              void* d_out, int out_size) {
    const float* values  = (const float*)d_in[0];
    const float* keys    = (const float*)d_in[1];
    const float* queries = (const float*)d_in[2];
    const float* Wv      = (const float*)d_in[3];
    const float* Wk      = (const float*)d_in[4];
    const float* Wq      = (const float*)d_in[5];
    const float* Wu      = (const float*)d_in[6];
    const float* bu      = (const float*)d_in[7];
    float* out = (float*)d_out;

    cudaFuncSetAttribute(colsum_kernel, cudaFuncAttributeMaxDynamicSharedMemorySize, CS_DYN);
    cudaFuncSetAttribute(av_kernel, cudaFuncAttributeMaxDynamicSharedMemorySize, AV_DYN);

    proj_kernel<<<dim3(8, 128, 3), 256>>>(values, keys, queries, Wv, Wk, Wq);
    colsum_kernel<<<dim3(16, 32), 256, CS_DYN>>>();
    av_kernel<<<dim3(16, 32), 256, AV_DYN>>>();
    unify_kernel<<<128, 256>>>(Wu, bu, out);
}

// round 5
// speedup vs baseline: 4.7286x; 1.0152x over previous
#include <cuda_runtime.h>
#include <cuda_fp16.h>
#include <cuda_bf16.h>
#include <stdint.h>

#define T_ 2048
#define E_ 64
#define H_ 8
#define HE_ 512
#define B_ 4
#define BH_ 32

// ---------------- device scratch ----------------
__device__ __align__(16) __half g_Q[(size_t)BH_ * T_ * E_];   // [bh][t][e], pre-scaled 1/8
__device__ __align__(16) __half g_K[(size_t)BH_ * T_ * E_];   // [bh][t][e]
__device__ __align__(16) __half g_V[(size_t)BH_ * E_ * T_];   // [bh][e][t]; rescaled in place by invz
__device__ __align__(16) __half g_P[(size_t)BH_ * T_ * T_];   // expS fp16, 256 MB
__device__ float g_cinvz[BH_ * T_];
__device__ __align__(16) __nv_bfloat16 g_ctxh[(size_t)B_ * T_ * HE_];  // ctx split-bf16 hi
__device__ __align__(16) __nv_bfloat16 g_ctxl[(size_t)B_ * T_ * HE_];  // ctx split-bf16 lo
__device__ __align__(16) __nv_bfloat16 g_Wuh[64 * 512];       // Wu^T split hi  [n=64][k=512]
__device__ __align__(16) __nv_bfloat16 g_Wul[64 * 512];       // Wu^T split lo

__device__ __forceinline__ uint32_t smem_u32(const void* p) {
    uint32_t a;
    asm("{ .reg .u64 t; cvta.to.shared.u64 t, %1; cvt.u32.u64 %0, t; }" : "=r"(a) : "l"(p));
    return a;
}
__device__ __forceinline__ void ldsm_x4(uint32_t* r, uint32_t addr) {
    asm volatile("ldmatrix.sync.aligned.m8n8.x4.shared.b16 {%0,%1,%2,%3}, [%4];"
                 : "=r"(r[0]), "=r"(r[1]), "=r"(r[2]), "=r"(r[3]) : "r"(addr));
}
__device__ __forceinline__ void ldsm_x2(uint32_t* r, uint32_t addr) {
    asm volatile("ldmatrix.sync.aligned.m8n8.x2.shared.b16 {%0,%1}, [%2];"
                 : "=r"(r[0]), "=r"(r[1]) : "r"(addr));
}
__device__ __forceinline__ void mma_f16(float* c, const uint32_t* a, const uint32_t* b) {
    asm volatile(
        "mma.sync.aligned.m16n8k16.row.col.f32.f16.f16.f32 "
        "{%0,%1,%2,%3}, {%4,%5,%6,%7}, {%8,%9}, {%0,%1,%2,%3};"
        : "+f"(c[0]), "+f"(c[1]), "+f"(c[2]), "+f"(c[3])
        : "r"(a[0]), "r"(a[1]), "r"(a[2]), "r"(a[3]), "r"(b[0]), "r"(b[1]));
}
__device__ __forceinline__ void mma_bf16(float* c, const uint32_t* a, const uint32_t* b) {
    asm volatile(
        "mma.sync.aligned.m16n8k16.row.col.f32.bf16.bf16.f32 "
        "{%0,%1,%2,%3}, {%4,%5,%6,%7}, {%8,%9}, {%0,%1,%2,%3};"
        : "+f"(c[0]), "+f"(c[1]), "+f"(c[2]), "+f"(c[3])
        : "r"(a[0]), "r"(a[1]), "r"(a[2]), "r"(a[3]), "r"(b[0]), "r"(b[1]));
}
__device__ __forceinline__ uint32_t pack_h2(float a, float b) {
    __half2 h = __floats2half2_rn(a, b);
    return *reinterpret_cast<uint32_t*>(&h);
}
__device__ __forceinline__ uint32_t pack_bf2(float a, float b) {
    __nv_bfloat162 h = __floats2bfloat162_rn(a, b);
    return *reinterpret_cast<uint32_t*>(&h);
}
#define CP16(dst, src) \
    asm volatile("cp.async.cg.shared.global [%0], [%1], 16;" :: "r"(dst), "l"(src))
#define CP_COMMIT() asm volatile("cp.async.commit_group;")
template <int N>
__device__ __forceinline__ void cp_wait() {
    asm volatile("cp.async.wait_group %0;" :: "n"(N));
}

#define RS 144   // 128B row + 16B pad
#define RS2 272  // 256B row + 16B pad

// ---------------------------------------------------------------------------
// K1: projections (fp32 FFMA, 64x64 tiles, K=64). z=0:V(transpose), 1:K, 2:Q/8
// ---------------------------------------------------------------------------
__global__ void proj_kernel(const float* __restrict__ Xv, const float* __restrict__ Xk,
                            const float* __restrict__ Xq, const float* __restrict__ Wv,
                            const float* __restrict__ Wk, const float* __restrict__ Wq) {
    const float* X;
    const float* W;
    if (blockIdx.z == 0)      { X = Xv; W = Wv; }
    else if (blockIdx.z == 1) { X = Xk; W = Wk; }
    else                      { X = Xq; W = Wq; }

    __shared__ __align__(16) float Xs[64][68];
    __shared__ __align__(16) float Ws[64][68];
    const int n0 = blockIdx.y * 64;
    const int h  = blockIdx.x;
    const int m0 = h * 64;
    const int b  = n0 >> 11;
    const int t0g = n0 & (T_ - 1);
    const int bh = b * 8 + h;
    const int tid = threadIdx.x;

    {
        const int r = tid >> 2, q = tid & 3;
        const float4* xs = reinterpret_cast<const float4*>(X + (size_t)(n0 + r) * 64) + q * 4;
        const float4* ws = reinterpret_cast<const float4*>(W + (size_t)r * HE_ + m0) + q * 4;
#pragma unroll
        for (int j = 0; j < 4; j++) {
            float4 v = xs[j];
            int k = q * 16 + j * 4;
            Xs[r][k] = v.x; Xs[r][k + 1] = v.y; Xs[r][k + 2] = v.z; Xs[r][k + 3] = v.w;
            float4 w = ws[j];
            Ws[r][k] = w.x; Ws[r][k + 1] = w.y; Ws[r][k + 2] = w.z; Ws[r][k + 3] = w.w;
        }
    }
    __syncthreads();

    const int tx = tid & 15, ty = tid >> 4;
    float acc[4][4] = {};
#pragma unroll 8
    for (int k = 0; k < 64; k++) {
        float a[4], bb[4];
#pragma unroll
        for (int r = 0; r < 4; r++) a[r] = Xs[ty * 4 + r][k];
#pragma unroll
        for (int c = 0; c < 4; c++) bb[c] = Ws[k][tx * 4 + c];
#pragma unroll
        for (int r = 0; r < 4; r++)
#pragma unroll
            for (int c = 0; c < 4; c++) acc[r][c] = fmaf(a[r], bb[c], acc[r][c]);
    }

    if (blockIdx.z == 0) {
        __syncthreads();
#pragma unroll
        for (int r = 0; r < 4; r++)
#pragma unroll
            for (int c = 0; c < 4; c++) Xs[tx * 4 + c][ty * 4 + r] = acc[r][c];
        __syncthreads();
        const int e = tid >> 2, seg = tid & 3;
        ushort hv[16];
#pragma unroll
        for (int j = 0; j < 16; j++) {
            __half hh = __float2half_rn(Xs[e][seg * 16 + j]);
            hv[j] = *reinterpret_cast<ushort*>(&hh);
        }
        size_t base = ((size_t)bh * 64 + e) * T_ + t0g + seg * 16;
        *reinterpret_cast<uint4*>(g_V + base)     = *reinterpret_cast<uint4*>(hv);
        *reinterpret_cast<uint4*>(g_V + base + 8) = *reinterpret_cast<uint4*>(hv + 8);
    } else {
        __half* O = (blockIdx.z == 1) ? g_K : g_Q;
        const float sc = (blockIdx.z == 2) ? 0.125f : 1.0f;
#pragma unroll
        for (int r = 0; r < 4; r++) {
            ushort hv[4];
#pragma unroll
            for (int c = 0; c < 4; c++) {
                __half hh = __float2half_rn(acc[r][c] * sc);
                hv[c] = *reinterpret_cast<ushort*>(&hh);
            }
            size_t base = ((size_t)bh * T_ + t0g + ty * 4 + r) * 64 + tx * 4;
            *reinterpret_cast<uint2*>(O + base) = *reinterpret_cast<uint2*>(hv);
        }
    }
}

// ---------------------------------------------------------------------------
// Wu prep: transpose + split-2 bf16:  g_Wu{h,l}[n][k] = split(Wu[k][n])
// ---------------------------------------------------------------------------
__global__ void wuprep_kernel(const float* __restrict__ Wu) {
    int idx = blockIdx.x * 256 + threadIdx.x;  // 32768 total
    int n = idx >> 9, k = idx & 511;
    float v = Wu[(size_t)k * 64 + n];
    __nv_bfloat16 hb = __float2bfloat16(v);
    g_Wuh[idx] = hb;
    g_Wul[idx] = __float2bfloat16(v - __bfloat162float(hb));
}

// ---------------------------------------------------------------------------
// K2: colsum. CTA=(i-block 128, bh). K resident; Q streamed (cp.async dual-buf).
// Per chunk: S via MMA, p = exp(s): store to g_P (fp16) + accumulate z[col].
// ---------------------------------------------------------------------------
#define CS_SK 0
#define CS_SQ0 (128 * RS)
#define CS_SQ1 (2 * 128 * RS)
#define CS_ZB (3 * 128 * RS)
#define CS_DYN (CS_ZB + 1024)
__global__ void __launch_bounds__(256) colsum_kernel() {
    extern __shared__ char sm[];
    const int tid = threadIdx.x, wid = tid >> 5, lane = tid & 31;
    const int bh = blockIdx.y;
    const int i0 = blockIdx.x * 128;
    const uint32_t sbase = smem_u32(sm);

    const __half* Qg = g_Q + (size_t)bh * T_ * 64;
    const __half* Kg = g_K + (size_t)bh * T_ * 64;
    float* zbuf = reinterpret_cast<float*>(sm + CS_ZB);

    // K resident (plain loads; covered by first sync)
#pragma unroll
    for (int j = 0; j < 4; j++) {
        int idx = j * 256 + tid;
        int row = idx >> 3, c = idx & 7;
        *reinterpret_cast<uint4*>(sm + CS_SK + row * RS + c * 16) =
            *reinterpret_cast<const uint4*>(Kg + (size_t)(i0 + row) * 64 + c * 8);
    }

    auto loadQ = [&](int tc, int buf) {
        const uint32_t dst0 = sbase + (buf ? CS_SQ1 : CS_SQ0);
#pragma unroll
        for (int j = 0; j < 4; j++) {
            int idx = j * 256 + tid;
            int row = idx >> 3, c = idx & 7;
            CP16(dst0 + row * RS + c * 16, Qg + (size_t)(tc * 128 + row) * 64 + c * 8);
        }
    };
    loadQ(0, 0);
    CP_COMMIT();

    const int wm = (wid & 1) * 64;
    const int wn = (wid >> 1) * 32;
    const int ar = (lane & 7) + ((lane >> 3) & 1) * 8;
    const int ac = (lane >> 4) * 16;
    const int brow = lane & 7;
    const int bcol = ((lane >> 3) & 1) * 16;
    const uint32_t aK = sbase + CS_SK;

    float z[8] = {};

    for (int tc = 0; tc < 16; tc++) {
        if (tc < 15) {
            loadQ(tc + 1, (tc + 1) & 1);
            CP_COMMIT();
            cp_wait<1>();
        } else {
            cp_wait<0>();
        }
        __syncthreads();

        const uint32_t aQ = sbase + ((tc & 1) ? CS_SQ1 : CS_SQ0);
        float acc[4][4][4] = {};
#pragma unroll
        for (int ks = 0; ks < 4; ks++) {
            uint32_t A[4][4], Bf[4][2];
#pragma unroll
            for (int mi = 0; mi < 4; mi++)
                ldsm_x4(A[mi], aQ + (uint32_t)((wm + mi * 16 + ar) * RS + ks * 32 + ac));
#pragma unroll
            for (int ni = 0; ni < 4; ni++)
                ldsm_x2(Bf[ni], aK + (uint32_t)((wn + ni * 8 + brow) * RS + ks * 32 + bcol));
#pragma unroll
            for (int mi = 0; mi < 4; mi++)
#pragma unroll
                for (int ni = 0; ni < 4; ni++) mma_f16(acc[mi][ni], A[mi], Bf[ni]);
        }

        // exp -> expS store + z accumulate
        __half* Pp = g_P + ((size_t)bh * T_ + tc * 128) * T_ + i0;
#pragma unroll
        for (int mi = 0; mi < 4; mi++)
#pragma unroll
            for (int ni = 0; ni < 4; ni++) {
                float p0 = __expf(acc[mi][ni][0]);
                float p1 = __expf(acc[mi][ni][1]);
                float p2 = __expf(acc[mi][ni][2]);
                float p3 = __expf(acc[mi][ni][3]);
                z[ni * 2]     += p0 + p2;
                z[ni * 2 + 1] += p1 + p3;
                int r = wm + mi * 16 + (lane >> 2);
                int c = wn + ni * 8 + (lane & 3) * 2;
                *reinterpret_cast<uint32_t*>(Pp + (size_t)r * T_ + c) = pack_h2(p0, p1);
                *reinterpret_cast<uint32_t*>(Pp + (size_t)(r + 8) * T_ + c) = pack_h2(p2, p3);
            }
        __syncthreads();
    }

    // reduce z over lanes sharing (lane & 3), then across warp pairs (same wn)
#pragma unroll
    for (int c = 0; c < 8; c++) {
        z[c] += __shfl_xor_sync(0xffffffffu, z[c], 4);
        z[c] += __shfl_xor_sync(0xffffffffu, z[c], 8);
        z[c] += __shfl_xor_sync(0xffffffffu, z[c], 16);
    }
    if (lane < 4) {
#pragma unroll
        for (int ni = 0; ni < 4; ni++) {
            zbuf[wid * 32 + ni * 8 + lane * 2]     = z[ni * 2];
            zbuf[wid * 32 + ni * 8 + lane * 2 + 1] = z[ni * 2 + 1];
        }
    }
    __syncthreads();
    if (tid < 128) {
        int col = tid;
        int wg = col >> 5, local = col & 31;
        float zt = zbuf[(2 * wg) * 32 + local] + zbuf[(2 * wg + 1) * 32 + local];
        g_cinvz[bh * T_ + i0 + col] = 1.0f / zt;
    }
}

// ---------------------------------------------------------------------------
// K3: rescale V in place: V[bh][e][i] *= invz[bh][i]
// ---------------------------------------------------------------------------
__global__ void rescale_kernel() {
    size_t idx = (size_t)blockIdx.x * 256 + threadIdx.x;  // each handles 8 halfs
    size_t g = idx * 8;
    int bh = (int)(g >> 17);
    int i = (int)(g & 2047);
    const float* iz = g_cinvz + bh * T_ + i;
    uint4 v = *reinterpret_cast<uint4*>(g_V + g);
    __half2* hp = reinterpret_cast<__half2*>(&v);
#pragma unroll
    for (int j = 0; j < 4; j++) {
        float2 f = __half22float2(hp[j]);
        f.x *= iz[j * 2];
        f.y *= iz[j * 2 + 1];
        hp[j] = __floats2half2_rn(f.x, f.y);
    }
    *reinterpret_cast<uint4*>(g_V + g) = v;
}

// ---------------------------------------------------------------------------
// K4: av = pure GEMM: O[t,e] = sum_i expS[t,i] * V'[e,i].  CTA=(t-block 128, bh),
// k chunks of 128 (cp.async dual-buffered). Output split-bf16 to ctxh/ctxl.
// ---------------------------------------------------------------------------
#define AV_A0 0
#define AV_A1 (128 * RS2)
#define AV_B0 (2 * 128 * RS2)
#define AV_B1 (2 * 128 * RS2 + 64 * RS2)
#define AV_DYN (2 * 128 * RS2 + 2 * 64 * RS2)
__global__ void __launch_bounds__(256) av_kernel() {
    extern __shared__ char sm[];
    const int tid = threadIdx.x, wid = tid >> 5, lane = tid & 31;
    const int bh = blockIdx.y, b = bh >> 3, h = bh & 7;
    const int t0 = blockIdx.x * 128;
    const uint32_t sbase = smem_u32(sm);

    const __half* Pg = g_P + (size_t)bh * T_ * T_;
    const __half* Vg = g_V + (size_t)bh * 64 * T_;

    auto loadA = [&](int kc, int buf) {
        const uint32_t dst0 = sbase + (buf ? AV_A1 : AV_A0);
#pragma unroll
        for (int j = 0; j < 8; j++) {
            int idx = j * 256 + tid;
            int row = idx >> 4, seg = idx & 15;
            CP16(dst0 + row * RS2 + seg * 16,
                 Pg + (size_t)(t0 + row) * T_ + kc * 128 + seg * 8);
        }
    };
    auto loadB = [&](int kc, int buf) {
        const uint32_t dst0 = sbase + (buf ? AV_B1 : AV_B0);
#pragma unroll
        for (int j = 0; j < 4; j++) {
            int idx = j * 256 + tid;
            int row = idx >> 4, seg = idx & 15;
            CP16(dst0 + row * RS2 + seg * 16,
                 Vg + (size_t)row * T_ + kc * 128 + seg * 8);
        }
    };
    loadA(0, 0);
    loadB(0, 0);
    CP_COMMIT();

    const int wm = (wid & 1) * 64;
    const int wn = (wid >> 1) * 16;
    const int ar = (lane & 7) + ((lane >> 3) & 1) * 8;
    const int ac = (lane >> 4) * 16;
    const int brow = lane & 7;
    const int bcol = ((lane >> 3) & 1) * 16;

    float acc[4][2][4] = {};

    for (int kc = 0; kc < 16; kc++) {
        if (kc < 15) {
            loadA(kc + 1, (kc + 1) & 1);
            loadB(kc + 1, (kc + 1) & 1);
            CP_COMMIT();
            cp_wait<1>();
        } else {
            cp_wait<0>();
        }
        __syncthreads();

        const uint32_t aA = sbase + ((kc & 1) ? AV_A1 : AV_A0);
        const uint32_t aB = sbase + ((kc & 1) ? AV_B1 : AV_B0);
#pragma unroll
        for (int ks = 0; ks < 8; ks++) {
            uint32_t A[4][4], Bf[2][2];
#pragma unroll
            for (int mi = 0; mi < 4; mi++)
                ldsm_x4(A[mi], aA + (uint32_t)((wm + mi * 16 + ar) * RS2 + ks * 32 + ac));
#pragma unroll
            for (int ni = 0; ni < 2; ni++)
                ldsm_x2(Bf[ni], aB + (uint32_t)((wn + ni * 8 + brow) * RS2 + ks * 32 + bcol));
#pragma unroll
            for (int mi = 0; mi < 4; mi++)
#pragma unroll
                for (int ni = 0; ni < 2; ni++) mma_f16(acc[mi][ni], A[mi], Bf[ni]);
        }
        __syncthreads();
    }

    // epilogue: split-bf16 -> g_ctxh / g_ctxl
    const int r0 = t0 + wm + (lane >> 2);
    const int c0 = h * 64 + wn + (lane & 3) * 2;
#pragma unroll
    for (int mi = 0; mi < 4; mi++)
#pragma unroll
        for (int ni = 0; ni < 2; ni++) {
#pragma unroll
            for (int half = 0; half < 2; half++) {
                float f0 = acc[mi][ni][half * 2];
                float f1 = acc[mi][ni][half * 2 + 1];
                __nv_bfloat16 h0 = __float2bfloat16(f0);
                __nv_bfloat16 h1 = __float2bfloat16(f1);
                float l0 = f0 - __bfloat162float(h0);
                float l1 = f1 - __bfloat162float(h1);
                size_t o = ((size_t)b * T_ + r0 + mi * 16 + half * 8) * HE_ + c0 + ni * 8;
                __nv_bfloat162 hh; hh.x = h0; hh.y = h1;
                *reinterpret_cast<uint32_t*>(g_ctxh + o) = *reinterpret_cast<uint32_t*>(&hh);
                *reinterpret_cast<uint32_t*>(g_ctxl + o) = pack_bf2(l0, l1);
            }
        }
}

// ---------------------------------------------------------------------------
// K5: unify via split-2 bf16 MMA: out = ctx @ Wu + bu.
// CTA = 64 rows, 128 CTAs; k=512 in 4 chunks of 128, dual-buffered.
// ---------------------------------------------------------------------------
#define UN_AH 0
#define UN_AL (64 * RS2)
#define UN_BH (2 * 64 * RS2)
#define UN_BL (3 * 64 * RS2)
#define UN_BUFSZ (4 * 64 * RS2)
#define UN_DYN (2 * UN_BUFSZ)
__global__ void __launch_bounds__(256) unify_kernel(const float* __restrict__ bu,
                                                    float* __restrict__ out) {
    extern __shared__ char sm[];
    const int tid = threadIdx.x, wid = tid >> 5, lane = tid & 31;
    const int n0 = blockIdx.x * 64;
    const uint32_t sbase = smem_u32(sm);

    auto loadChunk = [&](int kc, int buf) {
        const uint32_t d0 = sbase + buf * UN_BUFSZ;
#pragma unroll
        for (int j = 0; j < 4; j++) {
            int idx = j * 256 + tid;
            int row = idx >> 4, seg = idx & 15;
            size_t asrc = (size_t)(n0 + row) * HE_ + kc * 128 + seg * 8;
            CP16(d0 + UN_AH + row * RS2 + seg * 16, g_ctxh + asrc);
            CP16(d0 + UN_AL + row * RS2 + seg * 16, g_ctxl + asrc);
            size_t bsrc = (size_t)row * 512 + kc * 128 + seg * 8;
            CP16(d0 + UN_BH + row * RS2 + seg * 16, g_Wuh + bsrc);
            CP16(d0 + UN_BL + row * RS2 + seg * 16, g_Wul + bsrc);
        }
    };
    loadChunk(0, 0);
    CP_COMMIT();

    const int wn = wid * 8;
    const int ar = (lane & 7) + ((lane >> 3) & 1) * 8;
    const int ac = (lane >> 4) * 16;
    const int brow = lane & 7;
    const int bcol = ((lane >> 3) & 1) * 16;

    float acc[4][4] = {};

    for (int kc = 0; kc < 4; kc++) {
        if (kc < 3) {
            loadChunk(kc + 1, (kc + 1) & 1);
            CP_COMMIT();
            cp_wait<1>();
        } else {
            cp_wait<0>();
        }
        __syncthreads();

        const uint32_t d0 = sbase + (kc & 1) * UN_BUFSZ;
#pragma unroll
        for (int ks = 0; ks < 8; ks++) {
            uint32_t Ah[4][4], Al[4][4], Bh[2], Bl[2];
#pragma unroll
            for (int mi = 0; mi < 4; mi++) {
                uint32_t off = (uint32_t)((mi * 16 + ar) * RS2 + ks * 32 + ac);
                ldsm_x4(Ah[mi], d0 + UN_AH + off);
                ldsm_x4(Al[mi], d0 + UN_AL + off);
            }
            uint32_t boff = (uint32_t)((wn + brow) * RS2 + ks * 32 + bcol);
            ldsm_x2(Bh, d0 + UN_BH + boff);
            ldsm_x2(Bl, d0 + UN_BL + boff);
#pragma unroll
            for (int mi = 0; mi < 4; mi++) {
                mma_bf16(acc[mi], Ah[mi], Bh);
                mma_bf16(acc[mi], Ah[mi], Bl);
                mma_bf16(acc[mi], Al[mi], Bh);
            }
        }
        __syncthreads();
    }

    const int c0 = wn + (lane & 3) * 2;
    const float b0 = bu[c0], b1 = bu[c0 + 1];
#pragma unroll
    for (int mi = 0; mi < 4; mi++) {
        int r = n0 + mi * 16 + (lane >> 2);
        *reinterpret_cast<float2*>(out + (size_t)r * 64 + c0) =
            make_float2(acc[mi][0] + b0, acc[mi][1] + b1);
        *reinterpret_cast<float2*>(out + (size_t)(r + 8) * 64 + c0) =
            make_float2(acc[mi][2] + b0, acc[mi][3] + b1);
    }
}

extern "C" void kernel_launch(void* const* d_in, const int* in_sizes, int n_in,
                              void* d_out, int out_size) {
    const float* values  = (const float*)d_in[0];
    const float* keys    = (const float*)d_in[1];
    const float* queries = (const float*)d_in[2];
    const float* Wv      = (const float*)d_in[3];
    const float* Wk      = (const float*)d_in[4];
    const float* Wq      = (const float*)d_in[5];
    const float* Wu      = (const float*)d_in[6];
    const float* bu      = (const float*)d_in[7];
    float* out = (float*)d_out;

    cudaFuncSetAttribute(colsum_kernel, cudaFuncAttributeMaxDynamicSharedMemorySize, CS_DYN);
    cudaFuncSetAttribute(av_kernel, cudaFuncAttributeMaxDynamicSharedMemorySize, AV_DYN);
    cudaFuncSetAttribute(unify_kernel, cudaFuncAttributeMaxDynamicSharedMemorySize, UN_DYN);

    proj_kernel<<<dim3(8, 128, 3), 256>>>(values, keys, queries, Wv, Wk, Wq);
    wuprep_kernel<<<128, 256>>>(Wu);
    colsum_kernel<<<dim3(16, 32), 256, CS_DYN>>>();
    rescale_kernel<<<2048, 256>>>();
    av_kernel<<<dim3(16, 32), 256, AV_DYN>>>();
    unify_kernel<<<128, 256, UN_DYN>>>(bu, out);
}

// round 6
// speedup vs baseline: 5.1614x; 1.0915x over previous
#include <cuda_runtime.h>
#include <cuda_fp16.h>
#include <cuda_bf16.h>
#include <stdint.h>

#define T_ 2048
#define E_ 64
#define H_ 8
#define HE_ 512
#define B_ 4
#define BH_ 32

// ---------------- device scratch ----------------
__device__ __align__(16) __half g_Q[(size_t)BH_ * T_ * E_];   // [bh][t][e], pre-scaled 1/8
__device__ __align__(16) __half g_K[(size_t)BH_ * T_ * E_];   // [bh][t][e]
__device__ __align__(16) __half g_V[(size_t)BH_ * E_ * T_];   // [bh][e][t]; rescaled in colsum
__device__ __align__(16) __half g_P[(size_t)BH_ * T_ * T_];   // expS fp16
__device__ __align__(16) __nv_bfloat16 g_ctxh[(size_t)B_ * T_ * HE_];
__device__ __align__(16) __nv_bfloat16 g_ctxl[(size_t)B_ * T_ * HE_];
__device__ __align__(16) __nv_bfloat16 g_Wuh[64 * 512];       // Wu^T split hi [n][k]
__device__ __align__(16) __nv_bfloat16 g_Wul[64 * 512];

__device__ __forceinline__ uint32_t smem_u32(const void* p) {
    uint32_t a;
    asm("{ .reg .u64 t; cvta.to.shared.u64 t, %1; cvt.u32.u64 %0, t; }" : "=r"(a) : "l"(p));
    return a;
}
__device__ __forceinline__ void ldsm_x4(uint32_t* r, uint32_t addr) {
    asm volatile("ldmatrix.sync.aligned.m8n8.x4.shared.b16 {%0,%1,%2,%3}, [%4];"
                 : "=r"(r[0]), "=r"(r[1]), "=r"(r[2]), "=r"(r[3]) : "r"(addr));
}
__device__ __forceinline__ void ldsm_x2(uint32_t* r, uint32_t addr) {
    asm volatile("ldmatrix.sync.aligned.m8n8.x2.shared.b16 {%0,%1}, [%2];"
                 : "=r"(r[0]), "=r"(r[1]) : "r"(addr));
}
__device__ __forceinline__ void mma_f16(float* c, const uint32_t* a, const uint32_t* b) {
    asm volatile(
        "mma.sync.aligned.m16n8k16.row.col.f32.f16.f16.f32 "
        "{%0,%1,%2,%3}, {%4,%5,%6,%7}, {%8,%9}, {%0,%1,%2,%3};"
        : "+f"(c[0]), "+f"(c[1]), "+f"(c[2]), "+f"(c[3])
        : "r"(a[0]), "r"(a[1]), "r"(a[2]), "r"(a[3]), "r"(b[0]), "r"(b[1]));
}
__device__ __forceinline__ void mma_bf16(float* c, const uint32_t* a, const uint32_t* b) {
    asm volatile(
        "mma.sync.aligned.m16n8k16.row.col.f32.bf16.bf16.f32 "
        "{%0,%1,%2,%3}, {%4,%5,%6,%7}, {%8,%9}, {%0,%1,%2,%3};"
        : "+f"(c[0]), "+f"(c[1]), "+f"(c[2]), "+f"(c[3])
        : "r"(a[0]), "r"(a[1]), "r"(a[2]), "r"(a[3]), "r"(b[0]), "r"(b[1]));
}
__device__ __forceinline__ uint32_t pack_h2(float a, float b) {
    __half2 h = __floats2half2_rn(a, b);
    return *reinterpret_cast<uint32_t*>(&h);
}
__device__ __forceinline__ uint32_t pack_bf2(float a, float b) {
    __nv_bfloat162 h = __floats2bfloat162_rn(a, b);
    return *reinterpret_cast<uint32_t*>(&h);
}
#define CP16(dst, src) \
    asm volatile("cp.async.cg.shared.global [%0], [%1], 16;" :: "r"(dst), "l"(src))
#define CP_COMMIT() asm volatile("cp.async.commit_group;")
template <int N>
__device__ __forceinline__ void cp_wait() {
    asm volatile("cp.async.wait_group %0;" :: "n"(N));
}

#define RS 144   // 128B row + 16B pad
#define RS2 272  // 256B row + 16B pad

// ---------------------------------------------------------------------------
// K1: projections (fp32 FFMA). z=0:V(transpose), 1:K, 2:Q/8
// ---------------------------------------------------------------------------
__global__ void proj_kernel(const float* __restrict__ Xv, const float* __restrict__ Xk,
                            const float* __restrict__ Xq, const float* __restrict__ Wv,
                            const float* __restrict__ Wk, const float* __restrict__ Wq) {
    const float* X;
    const float* W;
    if (blockIdx.z == 0)      { X = Xv; W = Wv; }
    else if (blockIdx.z == 1) { X = Xk; W = Wk; }
    else                      { X = Xq; W = Wq; }

    __shared__ __align__(16) float Xs[64][68];
    __shared__ __align__(16) float Ws[64][68];
    const int n0 = blockIdx.y * 64;
    const int h  = blockIdx.x;
    const int m0 = h * 64;
    const int b  = n0 >> 11;
    const int t0g = n0 & (T_ - 1);
    const int bh = b * 8 + h;
    const int tid = threadIdx.x;

    {
        const int r = tid >> 2, q = tid & 3;
        const float4* xs = reinterpret_cast<const float4*>(X + (size_t)(n0 + r) * 64) + q * 4;
        const float4* ws = reinterpret_cast<const float4*>(W + (size_t)r * HE_ + m0) + q * 4;
#pragma unroll
        for (int j = 0; j < 4; j++) {
            float4 v = xs[j];
            int k = q * 16 + j * 4;
            Xs[r][k] = v.x; Xs[r][k + 1] = v.y; Xs[r][k + 2] = v.z; Xs[r][k + 3] = v.w;
            float4 w = ws[j];
            Ws[r][k] = w.x; Ws[r][k + 1] = w.y; Ws[r][k + 2] = w.z; Ws[r][k + 3] = w.w;
        }
    }
    __syncthreads();

    const int tx = tid & 15, ty = tid >> 4;
    float acc[4][4] = {};
#pragma unroll 8
    for (int k = 0; k < 64; k++) {
        float a[4], bb[4];
#pragma unroll
        for (int r = 0; r < 4; r++) a[r] = Xs[ty * 4 + r][k];
#pragma unroll
        for (int c = 0; c < 4; c++) bb[c] = Ws[k][tx * 4 + c];
#pragma unroll
        for (int r = 0; r < 4; r++)
#pragma unroll
            for (int c = 0; c < 4; c++) acc[r][c] = fmaf(a[r], bb[c], acc[r][c]);
    }

    if (blockIdx.z == 0) {
        __syncthreads();
#pragma unroll
        for (int r = 0; r < 4; r++)
#pragma unroll
            for (int c = 0; c < 4; c++) Xs[tx * 4 + c][ty * 4 + r] = acc[r][c];
        __syncthreads();
        const int e = tid >> 2, seg = tid & 3;
        ushort hv[16];
#pragma unroll
        for (int j = 0; j < 16; j++) {
            __half hh = __float2half_rn(Xs[e][seg * 16 + j]);
            hv[j] = *reinterpret_cast<ushort*>(&hh);
        }
        size_t base = ((size_t)bh * 64 + e) * T_ + t0g + seg * 16;
        *reinterpret_cast<uint4*>(g_V + base)     = *reinterpret_cast<uint4*>(hv);
        *reinterpret_cast<uint4*>(g_V + base + 8) = *reinterpret_cast<uint4*>(hv + 8);
    } else {
        __half* O = (blockIdx.z == 1) ? g_K : g_Q;
        const float sc = (blockIdx.z == 2) ? 0.125f : 1.0f;
#pragma unroll
        for (int r = 0; r < 4; r++) {
            ushort hv[4];
#pragma unroll
            for (int c = 0; c < 4; c++) {
                __half hh = __float2half_rn(acc[r][c] * sc);
                hv[c] = *reinterpret_cast<ushort*>(&hh);
            }
            size_t base = ((size_t)bh * T_ + t0g + ty * 4 + r) * 64 + tx * 4;
            *reinterpret_cast<uint2*>(O + base) = *reinterpret_cast<uint2*>(hv);
        }
    }
}

// ---------------------------------------------------------------------------
// Wu prep: transpose + split-2 bf16
// ---------------------------------------------------------------------------
__global__ void wuprep_kernel(const float* __restrict__ Wu) {
    int idx = blockIdx.x * 256 + threadIdx.x;
    int n = idx >> 9, k = idx & 511;
    float v = Wu[(size_t)k * 64 + n];
    __nv_bfloat16 hb = __float2bfloat16(v);
    g_Wuh[idx] = hb;
    g_Wul[idx] = __float2bfloat16(v - __bfloat162float(hb));
}

// ---------------------------------------------------------------------------
// K2: colsum. CTA=(i-block 128, bh). K resident; Q streamed (cp.async dual-buf).
// exp tiles staged through SMEM -> coalesced 16B stores to g_P.
// At the end: rescale V[bh][:, i0:i0+128] in place by invz.
// ---------------------------------------------------------------------------
#define CS_SK 0
#define CS_SQ0 (128 * RS)
#define CS_SQ1 (2 * 128 * RS)
#define CS_PS  (3 * 128 * RS)
#define CS_ZB  (3 * 128 * RS + 128 * RS2)
#define CS_DYN (CS_ZB + 2048)
__global__ void __launch_bounds__(256) colsum_kernel() {
    extern __shared__ char sm[];
    const int tid = threadIdx.x, wid = tid >> 5, lane = tid & 31;
    const int bh = blockIdx.y;
    const int i0 = blockIdx.x * 128;
    const uint32_t sbase = smem_u32(sm);

    const __half* Qg = g_Q + (size_t)bh * T_ * 64;
    const __half* Kg = g_K + (size_t)bh * T_ * 64;
    float* zbuf = reinterpret_cast<float*>(sm + CS_ZB);

    // K resident
#pragma unroll
    for (int j = 0; j < 4; j++) {
        int idx = j * 256 + tid;
        int row = idx >> 3, c = idx & 7;
        *reinterpret_cast<uint4*>(sm + CS_SK + row * RS + c * 16) =
            *reinterpret_cast<const uint4*>(Kg + (size_t)(i0 + row) * 64 + c * 8);
    }

    auto loadQ = [&](int tc, int buf) {
        const uint32_t dst0 = sbase + (buf ? CS_SQ1 : CS_SQ0);
#pragma unroll
        for (int j = 0; j < 4; j++) {
            int idx = j * 256 + tid;
            int row = idx >> 3, c = idx & 7;
            CP16(dst0 + row * RS + c * 16, Qg + (size_t)(tc * 128 + row) * 64 + c * 8);
        }
    };
    loadQ(0, 0);
    CP_COMMIT();

    const int wm = (wid & 1) * 64;
    const int wn = (wid >> 1) * 32;
    const int ar = (lane & 7) + ((lane >> 3) & 1) * 8;
    const int ac = (lane >> 4) * 16;
    const int bB = 8 * ((lane >> 4) & 1) + (lane & 7);   // fused-B row offset
    const int bK = ((lane >> 3) & 1) * 16;               // fused-B k-col offset
    const uint32_t aK = sbase + CS_SK;

    float z[8] = {};

    for (int tc = 0; tc < 16; tc++) {
        if (tc < 15) {
            loadQ(tc + 1, (tc + 1) & 1);
            CP_COMMIT();
            cp_wait<1>();
        } else {
            cp_wait<0>();
        }
        __syncthreads();

        const uint32_t aQ = sbase + ((tc & 1) ? CS_SQ1 : CS_SQ0);
        float acc[4][4][4] = {};
#pragma unroll
        for (int ks = 0; ks < 4; ks++) {
            uint32_t A[4][4], Bf[4][2];
#pragma unroll
            for (int mi = 0; mi < 4; mi++)
                ldsm_x4(A[mi], aQ + (uint32_t)((wm + mi * 16 + ar) * RS + ks * 32 + ac));
#pragma unroll
            for (int pr = 0; pr < 2; pr++)
                ldsm_x4(&Bf[pr * 2][0],
                        aK + (uint32_t)((wn + pr * 16 + bB) * RS + ks * 32 + bK));
#pragma unroll
            for (int mi = 0; mi < 4; mi++)
#pragma unroll
                for (int ni = 0; ni < 4; ni++) mma_f16(acc[mi][ni], A[mi], Bf[ni]);
        }

        // exp -> SMEM stage + z accumulate
#pragma unroll
        for (int mi = 0; mi < 4; mi++)
#pragma unroll
            for (int ni = 0; ni < 4; ni++) {
                float p0 = __expf(acc[mi][ni][0]);
                float p1 = __expf(acc[mi][ni][1]);
                float p2 = __expf(acc[mi][ni][2]);
                float p3 = __expf(acc[mi][ni][3]);
                z[ni * 2]     += p0 + p2;
                z[ni * 2 + 1] += p1 + p3;
                int r = wm + mi * 16 + (lane >> 2);
                int cB = (wn + ni * 8 + (lane & 3) * 2) * 2;  // byte offset in row
                *reinterpret_cast<uint32_t*>(sm + CS_PS + r * RS2 + cB) = pack_h2(p0, p1);
                *reinterpret_cast<uint32_t*>(sm + CS_PS + (r + 8) * RS2 + cB) = pack_h2(p2, p3);
            }
        __syncthreads();

        // coalesced copy stage -> g_P
        __half* Pp = g_P + ((size_t)bh * T_ + tc * 128) * T_ + i0;
#pragma unroll
        for (int j = 0; j < 8; j++) {
            int idx = j * 256 + tid;
            int row = idx >> 4, seg = idx & 15;
            *reinterpret_cast<uint4*>(Pp + (size_t)row * T_ + seg * 8) =
                *reinterpret_cast<uint4*>(sm + CS_PS + row * RS2 + seg * 16);
        }
    }

    // reduce z: lanes sharing (lane & 3), then warp pairs
#pragma unroll
    for (int c = 0; c < 8; c++) {
        z[c] += __shfl_xor_sync(0xffffffffu, z[c], 4);
        z[c] += __shfl_xor_sync(0xffffffffu, z[c], 8);
        z[c] += __shfl_xor_sync(0xffffffffu, z[c], 16);
    }
    if (lane < 4) {
#pragma unroll
        for (int ni = 0; ni < 4; ni++) {
            zbuf[wid * 32 + ni * 8 + lane * 2]     = z[ni * 2];
            zbuf[wid * 32 + ni * 8 + lane * 2 + 1] = z[ni * 2 + 1];
        }
    }
    __syncthreads();
    if (tid < 128) {
        int wg = tid >> 5, local = tid & 31;
        float zt = zbuf[(2 * wg) * 32 + local] + zbuf[(2 * wg + 1) * 32 + local];
        zbuf[256 + tid] = 1.0f / zt;
    }
    __syncthreads();

    // rescale V[bh][e][i0..i0+128] in place
    const float* invz = zbuf + 256;
    __half* Vp = g_V + (size_t)bh * 64 * T_ + i0;
#pragma unroll
    for (int j = 0; j < 4; j++) {
        int idx = j * 256 + tid;
        int e = idx >> 4, seg = idx & 15;
        __half* vp = Vp + (size_t)e * T_ + seg * 8;
        uint4 v = *reinterpret_cast<uint4*>(vp);
        __half2* hp = reinterpret_cast<__half2*>(&v);
#pragma unroll
        for (int q = 0; q < 4; q++) {
            float2 f = __half22float2(hp[q]);
            f.x *= invz[seg * 8 + q * 2];
            f.y *= invz[seg * 8 + q * 2 + 1];
            hp[q] = __floats2half2_rn(f.x, f.y);
        }
        *reinterpret_cast<uint4*>(vp) = v;
    }
}

// ---------------------------------------------------------------------------
// K3: av = pure GEMM: O[t,e] = sum_i P[t,i] * V'[e,i]
// ---------------------------------------------------------------------------
#define AV_A0 0
#define AV_A1 (128 * RS2)
#define AV_B0 (2 * 128 * RS2)
#define AV_B1 (2 * 128 * RS2 + 64 * RS2)
#define AV_DYN (2 * 128 * RS2 + 2 * 64 * RS2)
__global__ void __launch_bounds__(256) av_kernel() {
    extern __shared__ char sm[];
    const int tid = threadIdx.x, wid = tid >> 5, lane = tid & 31;
    const int bh = blockIdx.y, b = bh >> 3, h = bh & 7;
    const int t0 = blockIdx.x * 128;
    const uint32_t sbase = smem_u32(sm);

    const __half* Pg = g_P + (size_t)bh * T_ * T_;
    const __half* Vg = g_V + (size_t)bh * 64 * T_;

    auto loadA = [&](int kc, int buf) {
        const uint32_t dst0 = sbase + (buf ? AV_A1 : AV_A0);
#pragma unroll
        for (int j = 0; j < 8; j++) {
            int idx = j * 256 + tid;
            int row = idx >> 4, seg = idx & 15;
            CP16(dst0 + row * RS2 + seg * 16,
                 Pg + (size_t)(t0 + row) * T_ + kc * 128 + seg * 8);
        }
    };
    auto loadB = [&](int kc, int buf) {
        const uint32_t dst0 = sbase + (buf ? AV_B1 : AV_B0);
#pragma unroll
        for (int j = 0; j < 4; j++) {
            int idx = j * 256 + tid;
            int row = idx >> 4, seg = idx & 15;
            CP16(dst0 + row * RS2 + seg * 16,
                 Vg + (size_t)row * T_ + kc * 128 + seg * 8);
        }
    };
    loadA(0, 0);
    loadB(0, 0);
    CP_COMMIT();

    const int wm = (wid & 1) * 64;
    const int wn = (wid >> 1) * 16;
    const int ar = (lane & 7) + ((lane >> 3) & 1) * 8;
    const int ac = (lane >> 4) * 16;
    const int bB = 8 * ((lane >> 4) & 1) + (lane & 7);
    const int bK = ((lane >> 3) & 1) * 16;

    float acc[4][2][4] = {};

    for (int kc = 0; kc < 16; kc++) {
        if (kc < 15) {
            loadA(kc + 1, (kc + 1) & 1);
            loadB(kc + 1, (kc + 1) & 1);
            CP_COMMIT();
            cp_wait<1>();
        } else {
            cp_wait<0>();
        }
        __syncthreads();

        const uint32_t aA = sbase + ((kc & 1) ? AV_A1 : AV_A0);
        const uint32_t aB = sbase + ((kc & 1) ? AV_B1 : AV_B0);
#pragma unroll
        for (int ks = 0; ks < 8; ks++) {
            uint32_t A[4][4], Bf[2][2];
#pragma unroll
            for (int mi = 0; mi < 4; mi++)
                ldsm_x4(A[mi], aA + (uint32_t)((wm + mi * 16 + ar) * RS2 + ks * 32 + ac));
            ldsm_x4(&Bf[0][0], aB + (uint32_t)((wn + bB) * RS2 + ks * 32 + bK));
#pragma unroll
            for (int mi = 0; mi < 4; mi++)
#pragma unroll
                for (int ni = 0; ni < 2; ni++) mma_f16(acc[mi][ni], A[mi], Bf[ni]);
        }
        __syncthreads();
    }

    // epilogue: split-bf16 -> g_ctxh / g_ctxl
    const int r0 = t0 + wm + (lane >> 2);
    const int c0 = h * 64 + wn + (lane & 3) * 2;
#pragma unroll
    for (int mi = 0; mi < 4; mi++)
#pragma unroll
        for (int ni = 0; ni < 2; ni++) {
#pragma unroll
            for (int half = 0; half < 2; half++) {
                float f0 = acc[mi][ni][half * 2];
                float f1 = acc[mi][ni][half * 2 + 1];
                __nv_bfloat16 h0 = __float2bfloat16(f0);
                __nv_bfloat16 h1 = __float2bfloat16(f1);
                float l0 = f0 - __bfloat162float(h0);
                float l1 = f1 - __bfloat162float(h1);
                size_t o = ((size_t)b * T_ + r0 + mi * 16 + half * 8) * HE_ + c0 + ni * 8;
                __nv_bfloat162 hh; hh.x = h0; hh.y = h1;
                *reinterpret_cast<uint32_t*>(g_ctxh + o) = *reinterpret_cast<uint32_t*>(&hh);
                *reinterpret_cast<uint32_t*>(g_ctxl + o) = pack_bf2(l0, l1);
            }
        }
}

// ---------------------------------------------------------------------------
// K4: unify via split-2 bf16 MMA: out = ctx @ Wu + bu
// ---------------------------------------------------------------------------
#define UN_AH 0
#define UN_AL (64 * RS2)
#define UN_BH (2 * 64 * RS2)
#define UN_BL (3 * 64 * RS2)
#define UN_BUFSZ (4 * 64 * RS2)
#define UN_DYN (2 * UN_BUFSZ)
__global__ void __launch_bounds__(256) unify_kernel(const float* __restrict__ bu,
                                                    float* __restrict__ out) {
    extern __shared__ char sm[];
    const int tid = threadIdx.x, wid = tid >> 5, lane = tid & 31;
    const int n0 = blockIdx.x * 64;
    const uint32_t sbase = smem_u32(sm);

    auto loadChunk = [&](int kc, int buf) {
        const uint32_t d0 = sbase + buf * UN_BUFSZ;
#pragma unroll
        for (int j = 0; j < 4; j++) {
            int idx = j * 256 + tid;
            int row = idx >> 4, seg = idx & 15;
            size_t asrc = (size_t)(n0 + row) * HE_ + kc * 128 + seg * 8;
            CP16(d0 + UN_AH + row * RS2 + seg * 16, g_ctxh + asrc);
            CP16(d0 + UN_AL + row * RS2 + seg * 16, g_ctxl + asrc);
            size_t bsrc = (size_t)row * 512 + kc * 128 + seg * 8;
            CP16(d0 + UN_BH + row * RS2 + seg * 16, g_Wuh + bsrc);
            CP16(d0 + UN_BL + row * RS2 + seg * 16, g_Wul + bsrc);
        }
    };
    loadChunk(0, 0);
    CP_COMMIT();

    const int wn = wid * 8;
    const int ar = (lane & 7) + ((lane >> 3) & 1) * 8;
    const int ac = (lane >> 4) * 16;
    const int brow = lane & 7;
    const int bcol = ((lane >> 3) & 1) * 16;

    float acc[4][4] = {};

    for (int kc = 0; kc < 4; kc++) {
        if (kc < 3) {
            loadChunk(kc + 1, (kc + 1) & 1);
            CP_COMMIT();
            cp_wait<1>();
        } else {
            cp_wait<0>();
        }
        __syncthreads();

        const uint32_t d0 = sbase + (kc & 1) * UN_BUFSZ;
#pragma unroll
        for (int ks = 0; ks < 8; ks++) {
            uint32_t Ah[4][4], Al[4][4], Bh[2], Bl[2];
#pragma unroll
            for (int mi = 0; mi < 4; mi++) {
                uint32_t off = (uint32_t)((mi * 16 + ar) * RS2 + ks * 32 + ac);
                ldsm_x4(Ah[mi], d0 + UN_AH + off);
                ldsm_x4(Al[mi], d0 + UN_AL + off);
            }
            uint32_t boff = (uint32_t)((wn + brow) * RS2 + ks * 32 + bcol);
            ldsm_x2(Bh, d0 + UN_BH + boff);
            ldsm_x2(Bl, d0 + UN_BL + boff);
#pragma unroll
            for (int mi = 0; mi < 4; mi++) {
                mma_bf16(acc[mi], Ah[mi], Bh);
                mma_bf16(acc[mi], Ah[mi], Bl);
                mma_bf16(acc[mi], Al[mi], Bh);
            }
        }
        __syncthreads();
    }

    const int c0 = wn + (lane & 3) * 2;
    const float b0 = bu[c0], b1 = bu[c0 + 1];
#pragma unroll
    for (int mi = 0; mi < 4; mi++) {
        int r = n0 + mi * 16 + (lane >> 2);
        *reinterpret_cast<float2*>(out + (size_t)r * 64 + c0) =
            make_float2(acc[mi][0] + b0, acc[mi][1] + b1);
        *reinterpret_cast<float2*>(out + (size_t)(r + 8) * 64 + c0) =
            make_float2(acc[mi][2] + b0, acc[mi][3] + b1);
    }
}

extern "C" void kernel_launch(void* const* d_in, const int* in_sizes, int n_in,
                              void* d_out, int out_size) {
    const float* values  = (const float*)d_in[0];
    const float* keys    = (const float*)d_in[1];
    const float* queries = (const float*)d_in[2];
    const float* Wv      = (const float*)d_in[3];
    const float* Wk      = (const float*)d_in[4];
    const float* Wq      = (const float*)d_in[5];
    const float* Wu      = (const float*)d_in[6];
    const float* bu      = (const float*)d_in[7];
    float* out = (float*)d_out;

    cudaFuncSetAttribute(colsum_kernel, cudaFuncAttributeMaxDynamicSharedMemorySize, CS_DYN);
    cudaFuncSetAttribute(av_kernel, cudaFuncAttributeMaxDynamicSharedMemorySize, AV_DYN);
    cudaFuncSetAttribute(unify_kernel, cudaFuncAttributeMaxDynamicSharedMemorySize, UN_DYN);

    proj_kernel<<<dim3(8, 128, 3), 256>>>(values, keys, queries, Wv, Wk, Wq);
    wuprep_kernel<<<128, 256>>>(Wu);
    colsum_kernel<<<dim3(16, 32), 256, CS_DYN>>>();
    av_kernel<<<dim3(16, 32), 256, AV_DYN>>>();
    unify_kernel<<<128, 256, UN_DYN>>>(bu, out);
}

// round 8
// speedup vs baseline: 5.6506x; 1.0948x over previous
#include <cuda_runtime.h>
#include <cuda_fp16.h>
#include <cuda_bf16.h>
#include <stdint.h>

#define T_ 2048
#define E_ 64
#define H_ 8
#define HE_ 512
#define B_ 4
#define BH_ 32

// ---------------- device scratch ----------------
__device__ __align__(16) __half g_Q[(size_t)BH_ * T_ * E_];   // [bh][t][e], pre-scaled 1/8
__device__ __align__(16) __half g_K[(size_t)BH_ * T_ * E_];   // [bh][t][e]
__device__ __align__(16) __half g_V[(size_t)BH_ * E_ * T_];   // [bh][e][t]; rescaled in colsum
__device__ __align__(16) __half g_P[(size_t)BH_ * T_ * T_];   // expS fp16
__device__ __align__(16) __nv_bfloat16 g_ctxh[(size_t)B_ * T_ * HE_];
__device__ __align__(16) __nv_bfloat16 g_ctxl[(size_t)B_ * T_ * HE_];
__device__ __align__(16) __nv_bfloat16 g_Wuh[64 * 512];       // Wu^T split hi [n][k]
__device__ __align__(16) __nv_bfloat16 g_Wul[64 * 512];

__device__ __forceinline__ uint32_t smem_u32(const void* p) {
    uint32_t a;
    asm("{ .reg .u64 t; cvta.to.shared.u64 t, %1; cvt.u32.u64 %0, t; }" : "=r"(a) : "l"(p));
    return a;
}
__device__ __forceinline__ void ldsm_x4(uint32_t* r, uint32_t addr) {
    asm volatile("ldmatrix.sync.aligned.m8n8.x4.shared.b16 {%0,%1,%2,%3}, [%4];"
                 : "=r"(r[0]), "=r"(r[1]), "=r"(r[2]), "=r"(r[3]) : "r"(addr));
}
__device__ __forceinline__ void ldsm_x2(uint32_t* r, uint32_t addr) {
    asm volatile("ldmatrix.sync.aligned.m8n8.x2.shared.b16 {%0,%1}, [%2];"
                 : "=r"(r[0]), "=r"(r[1]) : "r"(addr));
}
__device__ __forceinline__ void mma_f16(float* c, const uint32_t* a, const uint32_t* b) {
    asm volatile(
        "mma.sync.aligned.m16n8k16.row.col.f32.f16.f16.f32 "
        "{%0,%1,%2,%3}, {%4,%5,%6,%7}, {%8,%9}, {%0,%1,%2,%3};"
        : "+f"(c[0]), "+f"(c[1]), "+f"(c[2]), "+f"(c[3])
        : "r"(a[0]), "r"(a[1]), "r"(a[2]), "r"(a[3]), "r"(b[0]), "r"(b[1]));
}
__device__ __forceinline__ void mma_bf16(float* c, const uint32_t* a, const uint32_t* b) {
    asm volatile(
        "mma.sync.aligned.m16n8k16.row.col.f32.bf16.bf16.f32 "
        "{%0,%1,%2,%3}, {%4,%5,%6,%7}, {%8,%9}, {%0,%1,%2,%3};"
        : "+f"(c[0]), "+f"(c[1]), "+f"(c[2]), "+f"(c[3])
        : "r"(a[0]), "r"(a[1]), "r"(a[2]), "r"(a[3]), "r"(b[0]), "r"(b[1]));
}
__device__ __forceinline__ uint32_t pack_h2(float a, float b) {
    __half2 h = __floats2half2_rn(a, b);
    return *reinterpret_cast<uint32_t*>(&h);
}
__device__ __forceinline__ uint32_t pack_bf2(float a, float b) {
    __nv_bfloat162 h = __floats2bfloat162_rn(a, b);
    return *reinterpret_cast<uint32_t*>(&h);
}
#define CP16(dst, src) \
    asm volatile("cp.async.cg.shared.global [%0], [%1], 16;" :: "r"(dst), "l"(src))
#define CP_COMMIT() asm volatile("cp.async.commit_group;")
template <int N>
__device__ __forceinline__ void cp_wait() {
    asm volatile("cp.async.wait_group %0;" :: "n"(N));
}

#define RS 144   // 128B row + 16B pad
#define RS2 272  // 256B row + 16B pad

// ---------------------------------------------------------------------------
// K1: projections (fp32 FFMA). z=0:V(transpose), 1:K, 2:Q/8.  Rows split by n_base.
// ---------------------------------------------------------------------------
__global__ void proj_kernel(const float* __restrict__ Xv, const float* __restrict__ Xk,
                            const float* __restrict__ Xq, const float* __restrict__ Wv,
                            const float* __restrict__ Wk, const float* __restrict__ Wq,
                            int n_base) {
    const float* X;
    const float* W;
    if (blockIdx.z == 0)      { X = Xv; W = Wv; }
    else if (blockIdx.z == 1) { X = Xk; W = Wk; }
    else                      { X = Xq; W = Wq; }

    __shared__ __align__(16) float Xs[64][68];
    __shared__ __align__(16) float Ws[64][68];
    const int n0 = n_base + blockIdx.y * 64;
    const int h  = blockIdx.x;
    const int m0 = h * 64;
    const int b  = n0 >> 11;
    const int t0g = n0 & (T_ - 1);
    const int bh = b * 8 + h;
    const int tid = threadIdx.x;

    {
        const int r = tid >> 2, q = tid & 3;
        const float4* xs = reinterpret_cast<const float4*>(X + (size_t)(n0 + r) * 64) + q * 4;
        const float4* ws = reinterpret_cast<const float4*>(W + (size_t)r * HE_ + m0) + q * 4;
#pragma unroll
        for (int j = 0; j < 4; j++) {
            float4 v = xs[j];
            int k = q * 16 + j * 4;
            Xs[r][k] = v.x; Xs[r][k + 1] = v.y; Xs[r][k + 2] = v.z; Xs[r][k + 3] = v.w;
            float4 w = ws[j];
            Ws[r][k] = w.x; Ws[r][k + 1] = w.y; Ws[r][k + 2] = w.z; Ws[r][k + 3] = w.w;
        }
    }
    __syncthreads();

    const int tx = tid & 15, ty = tid >> 4;
    float acc[4][4] = {};
#pragma unroll 8
    for (int k = 0; k < 64; k++) {
        float a[4], bb[4];
#pragma unroll
        for (int r = 0; r < 4; r++) a[r] = Xs[ty * 4 + r][k];
#pragma unroll
        for (int c = 0; c < 4; c++) bb[c] = Ws[k][tx * 4 + c];
#pragma unroll
        for (int r = 0; r < 4; r++)
#pragma unroll
            for (int c = 0; c < 4; c++) acc[r][c] = fmaf(a[r], bb[c], acc[r][c]);
    }

    if (blockIdx.z == 0) {
        __syncthreads();
#pragma unroll
        for (int r = 0; r < 4; r++)
#pragma unroll
            for (int c = 0; c < 4; c++) Xs[tx * 4 + c][ty * 4 + r] = acc[r][c];
        __syncthreads();
        const int e = tid >> 2, seg = tid & 3;
        ushort hv[16];
#pragma unroll
        for (int j = 0; j < 16; j++) {
            __half hh = __float2half_rn(Xs[e][seg * 16 + j]);
            hv[j] = *reinterpret_cast<ushort*>(&hh);
        }
        size_t base = ((size_t)bh * 64 + e) * T_ + t0g + seg * 16;
        *reinterpret_cast<uint4*>(g_V + base)     = *reinterpret_cast<uint4*>(hv);
        *reinterpret_cast<uint4*>(g_V + base + 8) = *reinterpret_cast<uint4*>(hv + 8);
    } else {
        __half* O = (blockIdx.z == 1) ? g_K : g_Q;
        const float sc = (blockIdx.z == 2) ? 0.125f : 1.0f;
#pragma unroll
        for (int r = 0; r < 4; r++) {
            ushort hv[4];
#pragma unroll
            for (int c = 0; c < 4; c++) {
                __half hh = __float2half_rn(acc[r][c] * sc);
                hv[c] = *reinterpret_cast<ushort*>(&hh);
            }
            size_t base = ((size_t)bh * T_ + t0g + ty * 4 + r) * 64 + tx * 4;
            *reinterpret_cast<uint2*>(O + base) = *reinterpret_cast<uint2*>(hv);
        }
    }
}

// ---------------------------------------------------------------------------
// Wu prep: transpose + split-2 bf16
// ---------------------------------------------------------------------------
__global__ void wuprep_kernel(const float* __restrict__ Wu) {
    int idx = blockIdx.x * 256 + threadIdx.x;
    int n = idx >> 9, k = idx & 511;
    float v = Wu[(size_t)k * 64 + n];
    __nv_bfloat16 hb = __float2bfloat16(v);
    g_Wuh[idx] = hb;
    g_Wul[idx] = __float2bfloat16(v - __bfloat162float(hb));
}

// ---------------------------------------------------------------------------
// K2: colsum. CTA=(i-block 128, bh). K resident; Q streamed (cp.async dual-buf).
// exp tiles staged through SMEM -> coalesced 16B stores to g_P.
// At the end: rescale V[bh][:, i0:i0+128] in place by invz.
// ---------------------------------------------------------------------------
#define CS_SK 0
#define CS_SQ0 (128 * RS)
#define CS_SQ1 (2 * 128 * RS)
#define CS_PS  (3 * 128 * RS)
#define CS_ZB  (3 * 128 * RS + 128 * RS2)
#define CS_DYN (CS_ZB + 2048)
__global__ void __launch_bounds__(256) colsum_kernel(int bh_base) {
    extern __shared__ char sm[];
    const int tid = threadIdx.x, wid = tid >> 5, lane = tid & 31;
    const int bh = bh_base + blockIdx.y;
    const int i0 = blockIdx.x * 128;
    const uint32_t sbase = smem_u32(sm);

    const __half* Qg = g_Q + (size_t)bh * T_ * 64;
    const __half* Kg = g_K + (size_t)bh * T_ * 64;
    float* zbuf = reinterpret_cast<float*>(sm + CS_ZB);

    // K resident
#pragma unroll
    for (int j = 0; j < 4; j++) {
        int idx = j * 256 + tid;
        int row = idx >> 3, c = idx & 7;
        *reinterpret_cast<uint4*>(sm + CS_SK + row * RS + c * 16) =
            *reinterpret_cast<const uint4*>(Kg + (size_t)(i0 + row) * 64 + c * 8);
    }

    auto loadQ = [&](int tc, int buf) {
        const uint32_t dst0 = sbase + (buf ? CS_SQ1 : CS_SQ0);
#pragma unroll
        for (int j = 0; j < 4; j++) {
            int idx = j * 256 + tid;
            int row = idx >> 3, c = idx & 7;
            CP16(dst0 + row * RS + c * 16, Qg + (size_t)(tc * 128 + row) * 64 + c * 8);
        }
    };
    loadQ(0, 0);
    CP_COMMIT();

    const int wm = (wid & 1) * 64;
    const int wn = (wid >> 1) * 32;
    const int ar = (lane & 7) + ((lane >> 3) & 1) * 8;
    const int ac = (lane >> 4) * 16;
    const int bB = 8 * ((lane >> 4) & 1) + (lane & 7);
    const int bK = ((lane >> 3) & 1) * 16;
    const uint32_t aK = sbase + CS_SK;

    float z[8] = {};

    for (int tc = 0; tc < 16; tc++) {
        if (tc < 15) {
            loadQ(tc + 1, (tc + 1) & 1);
            CP_COMMIT();
            cp_wait<1>();
        } else {
            cp_wait<0>();
        }
        __syncthreads();

        const uint32_t aQ = sbase + ((tc & 1) ? CS_SQ1 : CS_SQ0);
        float acc[4][4][4] = {};
#pragma unroll
        for (int ks = 0; ks < 4; ks++) {
            uint32_t A[4][4], Bf[4][2];
#pragma unroll
            for (int mi = 0; mi < 4; mi++)
                ldsm_x4(A[mi], aQ + (uint32_t)((wm + mi * 16 + ar) * RS + ks * 32 + ac));
#pragma unroll
            for (int pr = 0; pr < 2; pr++)
                ldsm_x4(&Bf[pr * 2][0],
                        aK + (uint32_t)((wn + pr * 16 + bB) * RS + ks * 32 + bK));
#pragma unroll
            for (int mi = 0; mi < 4; mi++)
#pragma unroll
                for (int ni = 0; ni < 4; ni++) mma_f16(acc[mi][ni], A[mi], Bf[ni]);
        }

        // exp -> SMEM stage + z accumulate
#pragma unroll
        for (int mi = 0; mi < 4; mi++)
#pragma unroll
            for (int ni = 0; ni < 4; ni++) {
                float p0 = __expf(acc[mi][ni][0]);
                float p1 = __expf(acc[mi][ni][1]);
                float p2 = __expf(acc[mi][ni][2]);
                float p3 = __expf(acc[mi][ni][3]);
                z[ni * 2]     += p0 + p2;
                z[ni * 2 + 1] += p1 + p3;
                int r = wm + mi * 16 + (lane >> 2);
                int cB = (wn + ni * 8 + (lane & 3) * 2) * 2;
                *reinterpret_cast<uint32_t*>(sm + CS_PS + r * RS2 + cB) = pack_h2(p0, p1);
                *reinterpret_cast<uint32_t*>(sm + CS_PS + (r + 8) * RS2 + cB) = pack_h2(p2, p3);
            }
        __syncthreads();

        // coalesced copy stage -> g_P
        __half* Pp = g_P + ((size_t)bh * T_ + tc * 128) * T_ + i0;
#pragma unroll
        for (int j = 0; j < 8; j++) {
            int idx = j * 256 + tid;
            int row = idx >> 4, seg = idx & 15;
            *reinterpret_cast<uint4*>(Pp + (size_t)row * T_ + seg * 8) =
                *reinterpret_cast<uint4*>(sm + CS_PS + row * RS2 + seg * 16);
        }
    }

    // reduce z
#pragma unroll
    for (int c = 0; c < 8; c++) {
        z[c] += __shfl_xor_sync(0xffffffffu, z[c], 4);
        z[c] += __shfl_xor_sync(0xffffffffu, z[c], 8);
        z[c] += __shfl_xor_sync(0xffffffffu, z[c], 16);
    }
    if (lane < 4) {
#pragma unroll
        for (int ni = 0; ni < 4; ni++) {
            zbuf[wid * 32 + ni * 8 + lane * 2]     = z[ni * 2];
            zbuf[wid * 32 + ni * 8 + lane * 2 + 1] = z[ni * 2 + 1];
        }
    }
    __syncthreads();
    if (tid < 128) {
        int wg = tid >> 5, local = tid & 31;
        float zt = zbuf[(2 * wg) * 32 + local] + zbuf[(2 * wg + 1) * 32 + local];
        zbuf[256 + tid] = 1.0f / zt;
    }
    __syncthreads();

    // rescale V[bh][e][i0..i0+128] in place
    const float* invz = zbuf + 256;
    __half* Vp = g_V + (size_t)bh * 64 * T_ + i0;
#pragma unroll
    for (int j = 0; j < 4; j++) {
        int idx = j * 256 + tid;
        int e = idx >> 4, seg = idx & 15;
        __half* vp = Vp + (size_t)e * T_ + seg * 8;
        uint4 v = *reinterpret_cast<uint4*>(vp);
        __half2* hp = reinterpret_cast<__half2*>(&v);
#pragma unroll
        for (int q = 0; q < 4; q++) {
            float2 f = __half22float2(hp[q]);
            f.x *= invz[seg * 8 + q * 2];
            f.y *= invz[seg * 8 + q * 2 + 1];
            hp[q] = __floats2half2_rn(f.x, f.y);
        }
        *reinterpret_cast<uint4*>(vp) = v;
    }
}

// ---------------------------------------------------------------------------
// K3: av = pure GEMM: O[t,e] = sum_i P[t,i]*V'[e,i].  k-chunk 64, 2-stage,
// small SMEM (54 KB) for 3-4 CTAs/SM.
// ---------------------------------------------------------------------------
#define AV_A0 0
#define AV_A1 (128 * RS)
#define AV_B0 (2 * 128 * RS)
#define AV_B1 (2 * 128 * RS + 64 * RS)
#define AV_DYN (2 * 128 * RS + 2 * 64 * RS)
__global__ void __launch_bounds__(256) av_kernel(int bh_base) {
    extern __shared__ char sm[];
    const int tid = threadIdx.x, wid = tid >> 5, lane = tid & 31;
    const int bh = bh_base + blockIdx.y, b = bh >> 3, h = bh & 7;
    const int t0 = blockIdx.x * 128;
    const uint32_t sbase = smem_u32(sm);

    const __half* Pg = g_P + (size_t)bh * T_ * T_;
    const __half* Vg = g_V + (size_t)bh * 64 * T_;

    auto loadA = [&](int kc, int buf) {
        const uint32_t dst0 = sbase + (buf ? AV_A1 : AV_A0);
#pragma unroll
        for (int j = 0; j < 4; j++) {
            int idx = j * 256 + tid;
            int row = idx >> 3, c = idx & 7;
            CP16(dst0 + row * RS + c * 16,
                 Pg + (size_t)(t0 + row) * T_ + kc * 64 + c * 8);
        }
    };
    auto loadB = [&](int kc, int buf) {
        const uint32_t dst0 = sbase + (buf ? AV_B1 : AV_B0);
#pragma unroll
        for (int j = 0; j < 2; j++) {
            int idx = j * 256 + tid;
            int row = idx >> 3, c = idx & 7;
            CP16(dst0 + row * RS + c * 16,
                 Vg + (size_t)row * T_ + kc * 64 + c * 8);
        }
    };
    loadA(0, 0);
    loadB(0, 0);
    CP_COMMIT();

    const int wm = (wid & 1) * 64;
    const int wn = (wid >> 1) * 16;
    const int ar = (lane & 7) + ((lane >> 3) & 1) * 8;
    const int ac = (lane >> 4) * 16;
    const int bB = 8 * ((lane >> 4) & 1) + (lane & 7);
    const int bK = ((lane >> 3) & 1) * 16;

    float acc[4][2][4] = {};

    for (int kc = 0; kc < 32; kc++) {
        if (kc < 31) {
            loadA(kc + 1, (kc + 1) & 1);
            loadB(kc + 1, (kc + 1) & 1);
            CP_COMMIT();
            cp_wait<1>();
        } else {
            cp_wait<0>();
        }
        __syncthreads();

        const uint32_t aA = sbase + ((kc & 1) ? AV_A1 : AV_A0);
        const uint32_t aB = sbase + ((kc & 1) ? AV_B1 : AV_B0);
#pragma unroll
        for (int ks = 0; ks < 4; ks++) {
            uint32_t A[4][4], Bf[2][2];
#pragma unroll
            for (int mi = 0; mi < 4; mi++)
                ldsm_x4(A[mi], aA + (uint32_t)((wm + mi * 16 + ar) * RS + ks * 32 + ac));
            ldsm_x4(&Bf[0][0], aB + (uint32_t)((wn + bB) * RS + ks * 32 + bK));
#pragma unroll
            for (int mi = 0; mi < 4; mi++)
#pragma unroll
                for (int ni = 0; ni < 2; ni++) mma_f16(acc[mi][ni], A[mi], Bf[ni]);
        }
        __syncthreads();
    }

    // epilogue: split-bf16 -> g_ctxh / g_ctxl
    const int r0 = t0 + wm + (lane >> 2);
    const int c0 = h * 64 + wn + (lane & 3) * 2;
#pragma unroll
    for (int mi = 0; mi < 4; mi++)
#pragma unroll
        for (int ni = 0; ni < 2; ni++) {
#pragma unroll
            for (int half = 0; half < 2; half++) {
                float f0 = acc[mi][ni][half * 2];
                float f1 = acc[mi][ni][half * 2 + 1];
                __nv_bfloat16 h0 = __float2bfloat16(f0);
                __nv_bfloat16 h1 = __float2bfloat16(f1);
                float l0 = f0 - __bfloat162float(h0);
                float l1 = f1 - __bfloat162float(h1);
                size_t o = ((size_t)b * T_ + r0 + mi * 16 + half * 8) * HE_ + c0 + ni * 8;
                __nv_bfloat162 hh; hh.x = h0; hh.y = h1;
                *reinterpret_cast<uint32_t*>(g_ctxh + o) = *reinterpret_cast<uint32_t*>(&hh);
                *reinterpret_cast<uint32_t*>(g_ctxl + o) = pack_bf2(l0, l1);
            }
        }
}

// ---------------------------------------------------------------------------
// K4: unify via split-2 bf16 MMA: out = ctx @ Wu + bu
// ---------------------------------------------------------------------------
#define UN_AH 0
#define UN_AL (64 * RS2)
#define UN_BH (2 * 64 * RS2)
#define UN_BL (3 * 64 * RS2)
#define UN_BUFSZ (4 * 64 * RS2)
#define UN_DYN (2 * UN_BUFSZ)
__global__ void __launch_bounds__(256) unify_kernel(const float* __restrict__ bu,
                                                    float* __restrict__ out) {
    extern __shared__ char sm[];
    const int tid = threadIdx.x, wid = tid >> 5, lane = tid & 31;
    const int n0 = blockIdx.x * 64;
    const uint32_t sbase = smem_u32(sm);

    auto loadChunk = [&](int kc, int buf) {
        const uint32_t d0 = sbase + buf * UN_BUFSZ;
#pragma unroll
        for (int j = 0; j < 4; j++) {
            int idx = j * 256 + tid;
            int row = idx >> 4, seg = idx & 15;
            size_t asrc = (size_t)(n0 + row) * HE_ + kc * 128 + seg * 8;
            CP16(d0 + UN_AH + row * RS2 + seg * 16, g_ctxh + asrc);
            CP16(d0 + UN_AL + row * RS2 + seg * 16, g_ctxl + asrc);
            size_t bsrc = (size_t)row * 512 + kc * 128 + seg * 8;
            CP16(d0 + UN_BH + row * RS2 + seg * 16, g_Wuh + bsrc);
            CP16(d0 + UN_BL + row * RS2 + seg * 16, g_Wul + bsrc);
        }
    };
    loadChunk(0, 0);
    CP_COMMIT();

    const int wn = wid * 8;
    const int ar = (lane & 7) + ((lane >> 3) & 1) * 8;
    const int ac = (lane >> 4) * 16;
    const int brow = lane & 7;
    const int bcol = ((lane >> 3) & 1) * 16;

    float acc[4][4] = {};

    for (int kc = 0; kc < 4; kc++) {
        if (kc < 3) {
            loadChunk(kc + 1, (kc + 1) & 1);
            CP_COMMIT();
            cp_wait<1>();
        } else {
            cp_wait<0>();
        }
        __syncthreads();

        const uint32_t d0 = sbase + (kc & 1) * UN_BUFSZ;
#pragma unroll
        for (int ks = 0; ks < 8; ks++) {
            uint32_t Ah[4][4], Al[4][4], Bh[2], Bl[2];
#pragma unroll
            for (int mi = 0; mi < 4; mi++) {
                uint32_t off = (uint32_t)((mi * 16 + ar) * RS2 + ks * 32 + ac);
                ldsm_x4(Ah[mi], d0 + UN_AH + off);
                ldsm_x4(Al[mi], d0 + UN_AL + off);
            }
            uint32_t boff = (uint32_t)((wn + brow) * RS2 + ks * 32 + bcol);
            ldsm_x2(Bh, d0 + UN_BH + boff);
            ldsm_x2(Bl, d0 + UN_BL + boff);
#pragma unroll
            for (int mi = 0; mi < 4; mi++) {
                mma_bf16(acc[mi], Ah[mi], Bh);
                mma_bf16(acc[mi], Ah[mi], Bl);
                mma_bf16(acc[mi], Al[mi], Bh);
            }
        }
        __syncthreads();
    }

    const int c0 = wn + (lane & 3) * 2;
    const float b0 = bu[c0], b1 = bu[c0 + 1];
#pragma unroll
    for (int mi = 0; mi < 4; mi++) {
        int r = n0 + mi * 16 + (lane >> 2);
        *reinterpret_cast<float2*>(out + (size_t)r * 64 + c0) =
            make_float2(acc[mi][0] + b0, acc[mi][1] + b1);
        *reinterpret_cast<float2*>(out + (size_t)(r + 8) * 64 + c0) =
            make_float2(acc[mi][2] + b0, acc[mi][3] + b1);
    }
}

extern "C" void kernel_launch(void* const* d_in, const int* in_sizes, int n_in,
                              void* d_out, int out_size) {
    const float* values  = (const float*)d_in[0];
    const float* keys    = (const float*)d_in[1];
    const float* queries = (const float*)d_in[2];
    const float* Wv      = (const float*)d_in[3];
    const float* Wk      = (const float*)d_in[4];
    const float* Wq      = (const float*)d_in[5];
    const float* Wu      = (const float*)d_in[6];
    const float* bu      = (const float*)d_in[7];
    float* out = (float*)d_out;

    // One-time resource setup (first call = correctness run, BEFORE the
    // harness's pre-capture memory baseline). Reused on every later call so
    // no allocation happens during capture/replay/teardown windows.
    struct Res {
        cudaStream_t sA, sB;
        cudaEvent_t evRoot, evA, evB;
        Res() {
            cudaStreamCreateWithFlags(&sA, cudaStreamNonBlocking);
            cudaStreamCreateWithFlags(&sB, cudaStreamNonBlocking);
            cudaEventCreateWithFlags(&evRoot, cudaEventDisableTiming);
            cudaEventCreateWithFlags(&evA, cudaEventDisableTiming);
            cudaEventCreateWithFlags(&evB, cudaEventDisableTiming);
            cudaFuncSetAttribute(colsum_kernel, cudaFuncAttributeMaxDynamicSharedMemorySize, CS_DYN);
            cudaFuncSetAttribute(av_kernel, cudaFuncAttributeMaxDynamicSharedMemorySize, AV_DYN);
            cudaFuncSetAttribute(unify_kernel, cudaFuncAttributeMaxDynamicSharedMemorySize, UN_DYN);
        }
    };
    static Res res;

    // Fork two batch-half pipelines (b 0-1 / b 2-3) onto side streams.
    cudaEventRecord(res.evRoot, 0);
    cudaStreamWaitEvent(res.sA, res.evRoot, 0);
    cudaStreamWaitEvent(res.sB, res.evRoot, 0);

    // main stream: Wu prep runs concurrently with the forked halves
    wuprep_kernel<<<128, 256>>>(Wu);

    proj_kernel<<<dim3(8, 64, 3), 256, 0, res.sA>>>(values, keys, queries, Wv, Wk, Wq, 0);
    proj_kernel<<<dim3(8, 64, 3), 256, 0, res.sB>>>(values, keys, queries, Wv, Wk, Wq, 4096);

    colsum_kernel<<<dim3(16, 16), 256, CS_DYN, res.sA>>>(0);
    colsum_kernel<<<dim3(16, 16), 256, CS_DYN, res.sB>>>(16);

    av_kernel<<<dim3(16, 16), 256, AV_DYN, res.sA>>>(0);
    av_kernel<<<dim3(16, 16), 256, AV_DYN, res.sB>>>(16);

    cudaEventRecord(res.evA, res.sA);
    cudaEventRecord(res.evB, res.sB);
    cudaStreamWaitEvent(0, res.evA, 0);
    cudaStreamWaitEvent(0, res.evB, 0);

    unify_kernel<<<128, 256, UN_DYN>>>(bu, out);
}